// round 13
// baseline (speedup 1.0000x reference)
#include <cuda_runtime.h>
#include <cuda_bf16.h>
#include <math.h>
#include <stdint.h>

#define Nn   50000
#define Gg   100
#define NPGc 500
#define INf  128
#define Hh   256
#define Ee   800000
#define WSLOT (128 * 256)

// ---------------- scratch ----------------
__device__ float g_h   [Nn * Hh];
__device__ float g_xh  [Nn * Hh];
__device__ float g_xl  [Nn * Hh];
__device__ __nv_bfloat16 g_mb [Nn * Hh];
__device__ __nv_bfloat16 g_cb [Nn * Hh];
__device__ __nv_bfloat16 g_fbuf[Nn * Hh];
__device__ int   g_knn [Nn * 3];
__device__ int   g_cnt [Nn];
__device__ float g_dinv[Nn];
__device__ int   g_scan[Nn];
__device__ int   g_off [Nn];
__device__ int   g_fill[Nn];
__device__ int   g_bsum[256];
__device__ int   g_bbase[256];
__device__ int   g_esrc[Ee];
__device__ float g_ecoef[Ee];
__device__ float g_s1  [Gg * Hh];    // zero-init; finalize re-zeroes after read
__device__ float g_s2  [Gg * Hh];
__device__ float g_ac  [Gg * Hh];
__device__ float g_bc  [Gg * Hh];
__device__ float g_af  [Gg * Hh];
__device__ float g_bf  [Gg * Hh];
__device__ uint32_t g_wpack[6][WSLOT];
__device__ float g_ewh[INf * Hh];
__device__ float g_ewl[INf * Hh];

// ---------------- helpers ----------------
__device__ __forceinline__ uint32_t f2tf(float f) {
    uint32_t u;
    asm("cvt.rna.tf32.f32 %0, %1;" : "=r"(u) : "f"(f));
    return u;
}
__device__ __forceinline__ uint32_t packbf2(float lo, float hi) {
    __nv_bfloat162 p = __floats2bfloat162_rn(lo, hi);
    return *(uint32_t*)&p;
}
__device__ __forceinline__ void mma16(float* c, const uint32_t* a, const uint32_t* b) {
    asm volatile(
        "mma.sync.aligned.m16n8k16.row.col.f32.bf16.bf16.f32 "
        "{%0,%1,%2,%3}, {%4,%5,%6,%7}, {%8,%9}, {%0,%1,%2,%3};"
        : "+f"(c[0]), "+f"(c[1]), "+f"(c[2]), "+f"(c[3])
        : "r"(a[0]), "r"(a[1]), "r"(a[2]), "r"(a[3]), "r"(b[0]), "r"(b[1]));
}
__device__ __forceinline__ void mma8(float* c, const uint32_t* a, const uint32_t* b) {
    asm volatile(
        "mma.sync.aligned.m16n8k8.row.col.f32.tf32.tf32.f32 "
        "{%0,%1,%2,%3}, {%4,%5,%6,%7}, {%8,%9}, {%0,%1,%2,%3};"
        : "+f"(c[0]), "+f"(c[1]), "+f"(c[2]), "+f"(c[3])
        : "r"(a[0]), "r"(a[1]), "r"(a[2]), "r"(a[3]), "r"(b[0]), "r"(b[1]));
}
__device__ __forceinline__ float4 bf4tof4(uint2 u) {
    __nv_bfloat162 a = *(__nv_bfloat162*)&u.x;
    __nv_bfloat162 b = *(__nv_bfloat162*)&u.y;
    return make_float4(__bfloat162float(a.x), __bfloat162float(a.y),
                       __bfloat162float(b.x), __bfloat162float(b.y));
}

// ---------------- small utility kernels ----------------
__global__ void zerof_k(float* p, int n) {
    int i = blockIdx.x * blockDim.x + threadIdx.x;
    if (i < n) p[i] = 0.0f;
}
__global__ void cnt_zero_k() {
    int i = blockIdx.x * blockDim.x + threadIdx.x;
    if (i < Nn) g_cnt[i] = 0;
}
__global__ void cnt_count_k(const int* __restrict__ dst) {
    int e = blockIdx.x * blockDim.x + threadIdx.x;
    if (e < Ee) atomicAdd(&g_cnt[dst[e]], 1);
}
__global__ void dinv_k() {
    int i = blockIdx.x * blockDim.x + threadIdx.x;
    if (i < Nn) g_dinv[i] = rsqrtf((float)g_cnt[i] + 1.0f);
}
__global__ void wpack_k(const float* __restrict__ W, int slot) {
    int i = blockIdx.x * blockDim.x + threadIdx.x;
    if (i >= WSLOT) return;
    int kk = i >> 8, n = i & 255;
    __nv_bfloat162 p = __floats2bfloat162_rn(W[(2 * kk) * 256 + n], W[(2 * kk + 1) * 256 + n]);
    g_wpack[slot][i] = *(uint32_t*)&p;
}
__global__ void embpack_k(const float* __restrict__ W) {
    int i = blockIdx.x * blockDim.x + threadIdx.x;
    if (i >= INf * Hh) return;
    float w = W[i];
    float h = __uint_as_float(f2tf(w));
    g_ewh[i] = h;
    g_ewl[i] = __uint_as_float(f2tf(w - h));
}

// ---------------- CSR build ----------------
__global__ void scan1_k() {
    __shared__ int sh[256];
    int i = blockIdx.x * 256 + threadIdx.x;
    int v = (i < Nn) ? g_cnt[i] : 0;
    sh[threadIdx.x] = v;
    __syncthreads();
    for (int off = 1; off < 256; off <<= 1) {
        int t = (threadIdx.x >= off) ? sh[threadIdx.x - off] : 0;
        __syncthreads();
        sh[threadIdx.x] += t;
        __syncthreads();
    }
    if (i < Nn) g_scan[i] = sh[threadIdx.x];
    if (threadIdx.x == 255) g_bsum[blockIdx.x] = sh[255];
}
__global__ void scan2_k(int nblk) {
    __shared__ int sh[256];
    int b = threadIdx.x;
    int v = (b < nblk) ? g_bsum[b] : 0;
    sh[b] = v;
    __syncthreads();
    for (int off = 1; off < 256; off <<= 1) {
        int t = (b >= off) ? sh[b - off] : 0;
        __syncthreads();
        sh[b] += t;
        __syncthreads();
    }
    if (b < nblk) g_bbase[b] = sh[b] - v;
}
__global__ void scan3_k() {
    int i = blockIdx.x * blockDim.x + threadIdx.x;
    if (i < Nn) {
        int off = g_scan[i] - g_cnt[i] + g_bbase[i >> 8];
        g_off[i] = off;
        g_fill[i] = off;
    }
}
__global__ void fill_k(const int* __restrict__ src, const int* __restrict__ dst) {
    int e = blockIdx.x * blockDim.x + threadIdx.x;
    if (e >= Ee) return;
    int s = src[e], d = dst[e];
    int p = atomicAdd(&g_fill[d], 1);
    g_esrc[p] = s;
    g_ecoef[p] = g_dinv[s] * g_dinv[d];
}

// ---------------- emb GEMM: tf32x3 tensor cores, h = x @ emb_W + b ----------------
__global__ __launch_bounds__(256) void emb_mma_k(
    const float* __restrict__ A, const float* __restrict__ bias, float* __restrict__ out)
{
    __shared__ uint32_t AsH[128][20], AsL[128][20];
    __shared__ uint32_t BsH[16][136], BsL[16][136];

    int tid = threadIdx.x;
    int wid = tid >> 5, lane = tid & 31;
    int m0 = blockIdx.y * 128, n0 = blockIdx.x * 128;
    int wm = (wid & 3) * 32, wn = (wid >> 2) * 64;
    int group = lane >> 2, tig = lane & 3;

    float acc[2][8][4];
#pragma unroll
    for (int mt = 0; mt < 2; mt++)
#pragma unroll
        for (int nt = 0; nt < 8; nt++)
#pragma unroll
            for (int q = 0; q < 4; q++) acc[mt][nt][q] = 0.0f;

    int arow = tid >> 1, acK = (tid & 1) * 8;
    int bkr = tid >> 4, bn8 = (tid & 15) * 8;
    bool vA = (m0 + arow) < Nn;
    float4 z4 = make_float4(0.f, 0.f, 0.f, 0.f);

    for (int kt = 0; kt < 8; kt++) {
        int k0 = kt * 16;
        float4 a0 = vA ? *(const float4*)(A + (size_t)(m0 + arow) * INf + k0 + acK) : z4;
        float4 a1 = vA ? *(const float4*)(A + (size_t)(m0 + arow) * INf + k0 + acK + 4) : z4;
        float av[8] = {a0.x, a0.y, a0.z, a0.w, a1.x, a1.y, a1.z, a1.w};
#pragma unroll
        for (int j = 0; j < 8; j++) {
            uint32_t hb = f2tf(av[j]);
            AsH[arow][acK + j] = hb;
            AsL[arow][acK + j] = f2tf(av[j] - __uint_as_float(hb));
        }
        const float* bh = g_ewh + (size_t)(k0 + bkr) * 256 + n0 + bn8;
        const float* bl = g_ewl + (size_t)(k0 + bkr) * 256 + n0 + bn8;
        *(float4*)&BsH[bkr][bn8]     = *(const float4*)(bh);
        *(float4*)&BsH[bkr][bn8 + 4] = *(const float4*)(bh + 4);
        *(float4*)&BsL[bkr][bn8]     = *(const float4*)(bl);
        *(float4*)&BsL[bkr][bn8 + 4] = *(const float4*)(bl + 4);
        __syncthreads();

#pragma unroll
        for (int ks = 0; ks < 2; ks++) {
            int kb = ks * 8;
            uint32_t ah[2][4], al[2][4];
#pragma unroll
            for (int mt = 0; mt < 2; mt++) {
                int r = wm + mt * 16 + group;
                ah[mt][0] = AsH[r][kb + tig];     ah[mt][1] = AsH[r + 8][kb + tig];
                ah[mt][2] = AsH[r][kb + tig + 4]; ah[mt][3] = AsH[r + 8][kb + tig + 4];
                al[mt][0] = AsL[r][kb + tig];     al[mt][1] = AsL[r + 8][kb + tig];
                al[mt][2] = AsL[r][kb + tig + 4]; al[mt][3] = AsL[r + 8][kb + tig + 4];
            }
            uint32_t bh2[8][2], bl2[8][2];
#pragma unroll
            for (int nt = 0; nt < 8; nt++) {
                int cc = wn + nt * 8 + group;
                bh2[nt][0] = BsH[kb + tig][cc]; bh2[nt][1] = BsH[kb + tig + 4][cc];
                bl2[nt][0] = BsL[kb + tig][cc]; bl2[nt][1] = BsL[kb + tig + 4][cc];
            }
#pragma unroll
            for (int mt = 0; mt < 2; mt++)
#pragma unroll
                for (int nt = 0; nt < 8; nt++) {
                    mma8(acc[mt][nt], ah[mt], bh2[nt]);
                    mma8(acc[mt][nt], ah[mt], bl2[nt]);
                    mma8(acc[mt][nt], al[mt], bh2[nt]);
                }
        }
        __syncthreads();
    }

#pragma unroll
    for (int mt = 0; mt < 2; mt++)
#pragma unroll
        for (int half = 0; half < 2; half++) {
            int row = m0 + wm + mt * 16 + group + half * 8;
            if (row >= Nn) continue;
#pragma unroll
            for (int nt = 0; nt < 8; nt++) {
                int col = n0 + wn + nt * 8 + 2 * tig;
                size_t base = (size_t)row * 256 + col;
                out[base]     = acc[mt][nt][half * 2 + 0] + bias[col];
                out[base + 1] = acc[mt][nt][half * 2 + 1] + bias[col + 1];
            }
        }
}

// ---------------- bf16 mma GEMM -> mb (bf16). NORMA: fused graphnorm+leaky on A ----------------
template <int NORMA, int ABF>
__global__ __launch_bounds__(256) void mmabf16_k(
    const void* __restrict__ Araw, const uint32_t* __restrict__ Bp,
    __nv_bfloat16* __restrict__ bout,
    const float* __restrict__ nAa, const float* __restrict__ nAb)
{
    __shared__ uint32_t As[128][20];
    __shared__ uint32_t Bs[16][136];

    int tid = threadIdx.x;
    int wid = tid >> 5, lane = tid & 31;
    int m0 = blockIdx.y * 128, n0 = blockIdx.x * 128;
    int wm = (wid & 3) * 32, wn = (wid >> 2) * 64;
    int group = lane >> 2, tig = lane & 3;

    float acc[2][8][4];
#pragma unroll
    for (int mt = 0; mt < 2; mt++)
#pragma unroll
        for (int nt = 0; nt < 8; nt++)
#pragma unroll
            for (int q = 0; q < 4; q++) acc[mt][nt][q] = 0.0f;

    int arow = tid >> 3, acK = (tid & 7) * 4;
    int bkr = tid >> 4, bn8 = (tid & 15) * 8;

    bool vAi[4];
    int ggA[4];
#pragma unroll
    for (int i = 0; i < 4; i++) {
        int r = m0 + arow + 32 * i;
        vAi[i] = r < Nn;
        ggA[i] = vAi[i] ? (r / NPGc) : 0;
    }

    const float* Af = (const float*)Araw;
    const __nv_bfloat16* Ab = (const __nv_bfloat16*)Araw;
    float4 paf[4];
    uint2 pab[4];
    uint4 pb[2];
    float4 z4 = make_float4(0.f, 0.f, 0.f, 0.f);
    uint2 z2 = make_uint2(0, 0);

#pragma unroll
    for (int i = 0; i < 4; i++) {
        int r = m0 + arow + 32 * i;
        if (ABF) pab[i] = vAi[i] ? *(const uint2*)(Ab + (size_t)r * 256 + acK) : z2;
        else     paf[i] = vAi[i] ? *(const float4*)(Af + (size_t)r * 256 + acK) : z4;
    }
#pragma unroll
    for (int j = 0; j < 2; j++)
        pb[j] = *(const uint4*)(Bp + (size_t)bkr * 256 + n0 + bn8 + 4 * j);

    for (int kt = 0; kt < 8; kt++) {
#pragma unroll
        for (int i = 0; i < 4; i++) {
            float4 w = ABF ? bf4tof4(pab[i]) : paf[i];
            if (NORMA) {
                if (vAi[i]) {
                    float4 a4 = *(const float4*)(nAa + ggA[i] * 256 + kt * 32 + acK);
                    float4 b4 = *(const float4*)(nAb + ggA[i] * 256 + kt * 32 + acK);
                    w.x = fmaf(w.x, a4.x, b4.x); w.x = w.x > 0.f ? w.x : 0.01f * w.x;
                    w.y = fmaf(w.y, a4.y, b4.y); w.y = w.y > 0.f ? w.y : 0.01f * w.y;
                    w.z = fmaf(w.z, a4.z, b4.z); w.z = w.z > 0.f ? w.z : 0.01f * w.z;
                    w.w = fmaf(w.w, a4.w, b4.w); w.w = w.w > 0.f ? w.w : 0.01f * w.w;
                }
            }
            As[arow + 32 * i][(acK >> 1) + 0] = packbf2(w.x, w.y);
            As[arow + 32 * i][(acK >> 1) + 1] = packbf2(w.z, w.w);
        }
#pragma unroll
        for (int j = 0; j < 2; j++)
            *(uint4*)&Bs[bkr][bn8 + 4 * j] = pb[j];
        __syncthreads();

        if (kt < 7) {
            int k0 = (kt + 1) * 32;
#pragma unroll
            for (int i = 0; i < 4; i++) {
                int r = m0 + arow + 32 * i;
                if (ABF) pab[i] = vAi[i] ? *(const uint2*)(Ab + (size_t)r * 256 + k0 + acK) : z2;
                else     paf[i] = vAi[i] ? *(const float4*)(Af + (size_t)r * 256 + k0 + acK) : z4;
            }
#pragma unroll
            for (int j = 0; j < 2; j++)
                pb[j] = *(const uint4*)(Bp + (size_t)((k0 >> 1) + bkr) * 256 + n0 + bn8 + 4 * j);
        }

#pragma unroll
        for (int s = 0; s < 2; s++) {
            uint32_t afr[2][4];
#pragma unroll
            for (int mt = 0; mt < 2; mt++) {
                int r = wm + mt * 16 + group;
                afr[mt][0] = As[r][s * 8 + tig];
                afr[mt][1] = As[r + 8][s * 8 + tig];
                afr[mt][2] = As[r][s * 8 + tig + 4];
                afr[mt][3] = As[r + 8][s * 8 + tig + 4];
            }
            uint32_t bfr[8][2];
#pragma unroll
            for (int nt = 0; nt < 8; nt++) {
                int cc = wn + nt * 8 + group;
                bfr[nt][0] = Bs[s * 8 + tig][cc];
                bfr[nt][1] = Bs[s * 8 + tig + 4][cc];
            }
#pragma unroll
            for (int mt = 0; mt < 2; mt++)
#pragma unroll
                for (int nt = 0; nt < 8; nt++) mma16(acc[mt][nt], afr[mt], bfr[nt]);
        }
        __syncthreads();
    }

#pragma unroll
    for (int mt = 0; mt < 2; mt++)
#pragma unroll
        for (int half = 0; half < 2; half++) {
            int row = m0 + wm + mt * 16 + group + half * 8;
            if (row >= Nn) continue;
#pragma unroll
            for (int nt = 0; nt < 8; nt++) {
                int col = n0 + wn + nt * 8 + 2 * tig;
                size_t base = (size_t)row * 256 + col;
                __nv_bfloat162 p = __floats2bfloat162_rn(acc[mt][nt][half * 2 + 0],
                                                         acc[mt][nt][half * 2 + 1]);
                *(__nv_bfloat162*)(bout + base) = p;
            }
        }
}

// ---------------- merged gate GEMM: K=512 + blend + residual + FUSED POOL ----------------
__global__ __launch_bounds__(256) void gate_k(
    const uint32_t* __restrict__ Bp, const float* __restrict__ gate_b,
    float* __restrict__ h, float* __restrict__ outp, float pw)
{
    __shared__ uint32_t As[128][20];
    __shared__ uint32_t Bs[16][136];
    __shared__ float pbin[2][128];

    int tid = threadIdx.x;
    int wid = tid >> 5, lane = tid & 31;
    int m0 = blockIdx.y * 128, n0 = blockIdx.x * 128;
    int wm = (wid & 3) * 32, wn = (wid >> 2) * 64;
    int group = lane >> 2, tig = lane & 3;
    int gbase = m0 / NPGc;

    pbin[tid >> 7][tid & 127] = 0.0f;

    float acc[2][8][4];
#pragma unroll
    for (int mt = 0; mt < 2; mt++)
#pragma unroll
        for (int nt = 0; nt < 8; nt++)
#pragma unroll
            for (int q = 0; q < 4; q++) acc[mt][nt][q] = 0.0f;

    int arow = tid >> 3, acK = (tid & 7) * 4;
    int bkr = tid >> 4, bn8 = (tid & 15) * 8;

    bool vAi[4];
    int ggA[4];
#pragma unroll
    for (int i = 0; i < 4; i++) {
        int r = m0 + arow + 32 * i;
        vAi[i] = r < Nn;
        ggA[i] = vAi[i] ? (r / NPGc) : 0;
    }

    uint2 pab[4];
    uint4 pb[2];
    uint2 z2 = make_uint2(0, 0);

#pragma unroll
    for (int i = 0; i < 4; i++) {
        int r = m0 + arow + 32 * i;
        pab[i] = vAi[i] ? *(const uint2*)(g_cb + (size_t)r * 256 + acK) : z2;
    }
#pragma unroll
    for (int j = 0; j < 2; j++)
        pb[j] = *(const uint4*)(Bp + (size_t)bkr * 256 + n0 + bn8 + 4 * j);

    for (int kt = 0; kt < 16; kt++) {
        int khalf = kt >> 3;                 // 0: c-branch, 1: f-branch
        int koff = (kt & 7) * 32;
        const float* na = khalf ? g_af : g_ac;
        const float* nb = khalf ? g_bf : g_bc;
#pragma unroll
        for (int i = 0; i < 4; i++) {
            float4 w = bf4tof4(pab[i]);
            if (vAi[i]) {
                float4 a4 = *(const float4*)(na + ggA[i] * 256 + koff + acK);
                float4 b4 = *(const float4*)(nb + ggA[i] * 256 + koff + acK);
                w.x = fmaf(w.x, a4.x, b4.x); w.x = w.x > 0.f ? w.x : 0.01f * w.x;
                w.y = fmaf(w.y, a4.y, b4.y); w.y = w.y > 0.f ? w.y : 0.01f * w.y;
                w.z = fmaf(w.z, a4.z, b4.z); w.z = w.z > 0.f ? w.z : 0.01f * w.z;
                w.w = fmaf(w.w, a4.w, b4.w); w.w = w.w > 0.f ? w.w : 0.01f * w.w;
            }
            As[arow + 32 * i][(acK >> 1) + 0] = packbf2(w.x, w.y);
            As[arow + 32 * i][(acK >> 1) + 1] = packbf2(w.z, w.w);
        }
#pragma unroll
        for (int j = 0; j < 2; j++)
            *(uint4*)&Bs[bkr][bn8 + 4 * j] = pb[j];
        __syncthreads();

        if (kt < 15) {
            int nk = kt + 1;
            const __nv_bfloat16* Asrc = (nk < 8) ? g_cb : g_fbuf;
            int nkoff = (nk & 7) * 32;
#pragma unroll
            for (int i = 0; i < 4; i++) {
                int r = m0 + arow + 32 * i;
                pab[i] = vAi[i] ? *(const uint2*)(Asrc + (size_t)r * 256 + nkoff + acK) : z2;
            }
#pragma unroll
            for (int j = 0; j < 2; j++)
                pb[j] = *(const uint4*)(Bp + (size_t)((nk * 16) + bkr) * 256 + n0 + bn8 + 4 * j);
        }

#pragma unroll
        for (int s = 0; s < 2; s++) {
            uint32_t afr[2][4];
#pragma unroll
            for (int mt = 0; mt < 2; mt++) {
                int r = wm + mt * 16 + group;
                afr[mt][0] = As[r][s * 8 + tig];
                afr[mt][1] = As[r + 8][s * 8 + tig];
                afr[mt][2] = As[r][s * 8 + tig + 4];
                afr[mt][3] = As[r + 8][s * 8 + tig + 4];
            }
            uint32_t bfr[8][2];
#pragma unroll
            for (int nt = 0; nt < 8; nt++) {
                int cc = wn + nt * 8 + group;
                bfr[nt][0] = Bs[s * 8 + tig][cc];
                bfr[nt][1] = Bs[s * 8 + tig + 4][cc];
            }
#pragma unroll
            for (int mt = 0; mt < 2; mt++)
#pragma unroll
                for (int nt = 0; nt < 8; nt++) mma16(acc[mt][nt], afr[mt], bfr[nt]);
        }
        __syncthreads();
    }

    // epilogue: g = sigmoid(acc + gate_b); hnew = g*leaky(norm_c(c)) + (1-g)*leaky(norm_f(f)) + h
    // fused pool: pbin[graph-bin][localcol] += hnew * pw
#pragma unroll
    for (int mt = 0; mt < 2; mt++)
#pragma unroll
        for (int half = 0; half < 2; half++) {
            int row = m0 + wm + mt * 16 + group + half * 8;
            if (row >= Nn) continue;
            int gg = row / NPGc;
            int bin = gg - gbase;
#pragma unroll
            for (int nt = 0; nt < 8; nt++) {
                int col = n0 + wn + nt * 8 + 2 * tig;
                size_t base = (size_t)row * 256 + col;
                int cb2 = gg * 256 + col;
                float s0 = acc[mt][nt][half * 2 + 0] + gate_b[col];
                float s1 = acc[mt][nt][half * 2 + 1] + gate_b[col + 1];
                float gt0 = 1.0f / (1.0f + expf(-s0));
                float gt1 = 1.0f / (1.0f + expf(-s1));
                __nv_bfloat162 cv = *(const __nv_bfloat162*)(g_cb + base);
                __nv_bfloat162 fv = *(const __nv_bfloat162*)(g_fbuf + base);
                float c0 = fmaf(__bfloat162float(cv.x), g_ac[cb2],     g_bc[cb2]);
                float c1 = fmaf(__bfloat162float(cv.y), g_ac[cb2 + 1], g_bc[cb2 + 1]);
                c0 = c0 > 0.f ? c0 : 0.01f * c0;
                c1 = c1 > 0.f ? c1 : 0.01f * c1;
                float f0 = fmaf(__bfloat162float(fv.x), g_af[cb2],     g_bf[cb2]);
                float f1 = fmaf(__bfloat162float(fv.y), g_af[cb2 + 1], g_bf[cb2 + 1]);
                f0 = f0 > 0.f ? f0 : 0.01f * f0;
                f1 = f1 > 0.f ? f1 : 0.01f * f1;
                float h0 = gt0 * c0 + (1.0f - gt0) * f0 + h[base];
                float h1 = gt1 * c1 + (1.0f - gt1) * f1 + h[base + 1];
                h[base]     = h0;
                h[base + 1] = h1;
                atomicAdd(&pbin[bin][col - n0],     h0 * pw);
                atomicAdd(&pbin[bin][col - n0 + 1], h1 * pw);
            }
        }
    __syncthreads();
    {
        int b2 = tid >> 7, lc = tid & 127;
        int gx = gbase + b2;
        if (gx < Gg) atomicAdd(&outp[gx * 256 + n0 + lc], pbin[b2][lc]);
    }
}

// ---------------- row normalize + tf32 hi/lo split ----------------
__global__ void rownorm_k() {
    int row = blockIdx.x;
    int t = threadIdx.x;
    float4 v = *(const float4*)(g_h + (size_t)row * Hh + t * 4);
    float s = v.x * v.x + v.y * v.y + v.z * v.z + v.w * v.w;
    __shared__ float sh[64];
    sh[t] = s;
    __syncthreads();
    for (int off = 32; off > 0; off >>= 1) {
        if (t < off) sh[t] += sh[t + off];
        __syncthreads();
    }
    float inv = 1.0f / (sqrtf(sh[0]) + 1e-12f);
    float n0 = v.x * inv, n1 = v.y * inv, n2 = v.z * inv, n3 = v.w * inv;
    float h0 = __uint_as_float(f2tf(n0));
    float h1 = __uint_as_float(f2tf(n1));
    float h2 = __uint_as_float(f2tf(n2));
    float h3 = __uint_as_float(f2tf(n3));
    *(float4*)(g_xh + (size_t)row * Hh + t * 4) = make_float4(h0, h1, h2, h3);
    *(float4*)(g_xl + (size_t)row * Hh + t * 4) =
        make_float4(__uint_as_float(f2tf(n0 - h0)), __uint_as_float(f2tf(n1 - h1)),
                    __uint_as_float(f2tf(n2 - h2)), __uint_as_float(f2tf(n3 - h3)));
}

// ---------------- top-3 insert ----------------
__device__ __forceinline__ void tk3(float v, int id, float* tv, int* ti) {
    if (v > tv[0] || (v == tv[0] && id < ti[0])) {
        tv[2] = tv[1]; ti[2] = ti[1];
        tv[1] = tv[0]; ti[1] = ti[0];
        tv[0] = v;     ti[0] = id;
    } else if (v > tv[1] || (v == tv[1] && id < ti[1])) {
        tv[2] = tv[1]; ti[2] = ti[1];
        tv[1] = v;     ti[1] = id;
    } else if (v > tv[2] || (v == tv[2] && id < ti[2])) {
        tv[2] = v;     ti[2] = id;
    }
}

// ---------------- fused 3xTF32 sim + top-3 (single-buffered, R9 layout) ----------------
__global__ __launch_bounds__(256) void simtopk_mma_k() {
    int g = blockIdx.y;
    int i0 = blockIdx.x * 64;
    const float* XH = g_xh + (size_t)g * NPGc * Hh;
    const float* XL = g_xl + (size_t)g * NPGc * Hh;
    int goff = g * NPGc;

    __shared__ uint32_t Ah[64][20], Al[64][20], Bh[128][20], Bl[128][20];
    __shared__ float redv[4][64][3];
    __shared__ int   redi[4][64][3];

    int tid = threadIdx.x;
    int wid = tid >> 5, lane = tid & 31;
    int group = lane >> 2, tig = lane & 3;
    int wrow = (wid & 1) * 32, wcol = (wid >> 1) * 32;

    float tv[4][3];
    int ti[4][3];
#pragma unroll
    for (int r = 0; r < 4; r++)
#pragma unroll
        for (int c = 0; c < 3; c++) { tv[r][c] = -1e30f; ti[r][c] = 0x7fffffff; }

    int rA = tid >> 2, qA = (tid & 3) * 4;
    int rB = tid >> 1, qB = (tid & 1) * 8;
    bool vA = (i0 + rA) < NPGc;
    const float* ahp = XH + (size_t)(i0 + rA) * Hh + qA;
    const float* alp = XL + (size_t)(i0 + rA) * Hh + qA;
    float4 zh = make_float4(0.f, 0.f, 0.f, 0.f);

    for (int jt = 0; jt < 4; jt++) {
        int j0 = jt * 128;
        bool vB = (j0 + rB) < NPGc;
        const float* bhp = XH + (size_t)(j0 + rB) * Hh + qB;
        const float* blp = XL + (size_t)(j0 + rB) * Hh + qB;

        float acc[2][4][4];
#pragma unroll
        for (int mt = 0; mt < 2; mt++)
#pragma unroll
            for (int nt = 0; nt < 4; nt++)
#pragma unroll
                for (int q = 0; q < 4; q++) acc[mt][nt][q] = 0.0f;

        for (int kt = 0; kt < 16; kt++) {
            int k0 = kt * 16;
            float4 va_h = vA ? *(const float4*)(ahp + k0) : zh;
            float4 va_l = vA ? *(const float4*)(alp + k0) : zh;
            *(uint4*)&Ah[rA][qA] = *(uint4*)&va_h;
            *(uint4*)&Al[rA][qA] = *(uint4*)&va_l;
            float4 vb_h0 = vB ? *(const float4*)(bhp + k0) : zh;
            float4 vb_h1 = vB ? *(const float4*)(bhp + k0 + 4) : zh;
            float4 vb_l0 = vB ? *(const float4*)(blp + k0) : zh;
            float4 vb_l1 = vB ? *(const float4*)(blp + k0 + 4) : zh;
            *(uint4*)&Bh[rB][qB]     = *(uint4*)&vb_h0;
            *(uint4*)&Bh[rB][qB + 4] = *(uint4*)&vb_h1;
            *(uint4*)&Bl[rB][qB]     = *(uint4*)&vb_l0;
            *(uint4*)&Bl[rB][qB + 4] = *(uint4*)&vb_l1;
            __syncthreads();

#pragma unroll
            for (int ks = 0; ks < 2; ks++) {
                int kb = ks * 8;
                uint32_t ah[2][4], al[2][4];
#pragma unroll
                for (int mt = 0; mt < 2; mt++) {
                    int r = wrow + mt * 16 + group;
                    ah[mt][0] = Ah[r][kb + tig];     ah[mt][1] = Ah[r + 8][kb + tig];
                    ah[mt][2] = Ah[r][kb + tig + 4]; ah[mt][3] = Ah[r + 8][kb + tig + 4];
                    al[mt][0] = Al[r][kb + tig];     al[mt][1] = Al[r + 8][kb + tig];
                    al[mt][2] = Al[r][kb + tig + 4]; al[mt][3] = Al[r + 8][kb + tig + 4];
                }
                uint32_t bh[4][2], bl[4][2];
#pragma unroll
                for (int nt = 0; nt < 4; nt++) {
                    int cc = wcol + nt * 8 + group;
                    bh[nt][0] = Bh[cc][kb + tig]; bh[nt][1] = Bh[cc][kb + tig + 4];
                    bl[nt][0] = Bl[cc][kb + tig]; bl[nt][1] = Bl[cc][kb + tig + 4];
                }
#pragma unroll
                for (int mt = 0; mt < 2; mt++)
#pragma unroll
                    for (int nt = 0; nt < 4; nt++) {
                        mma8(acc[mt][nt], ah[mt], bh[nt]);
                        mma8(acc[mt][nt], ah[mt], bl[nt]);
                        mma8(acc[mt][nt], al[mt], bh[nt]);
                    }
            }
            __syncthreads();
        }

#pragma unroll
        for (int mt = 0; mt < 2; mt++)
#pragma unroll
            for (int nt = 0; nt < 4; nt++)
#pragma unroll
                for (int q = 0; q < 4; q++) {
                    int half = q >> 1, cbit = q & 1;
                    int col = j0 + wcol + nt * 8 + 2 * tig + cbit;
                    if (col < NPGc) {
                        int r = mt * 2 + half;
                        tk3(acc[mt][nt][q], goff + col, tv[r], ti[r]);
                    }
                }
    }

#pragma unroll
    for (int x = 1; x <= 2; x <<= 1) {
#pragma unroll
        for (int r = 0; r < 4; r++) {
            float ov[3]; int oi[3];
#pragma unroll
            for (int c = 0; c < 3; c++) {
                ov[c] = __shfl_xor_sync(0xffffffff, tv[r][c], x);
                oi[c] = __shfl_xor_sync(0xffffffff, ti[r][c], x);
            }
#pragma unroll
            for (int c = 0; c < 3; c++) tk3(ov[c], oi[c], tv[r], ti[r]);
        }
    }

    if (tig == 0) {
        int w4 = wid >> 1;
#pragma unroll
        for (int r = 0; r < 4; r++) {
            int mt = r >> 1, half = r & 1;
            int rowl = wrow + mt * 16 + half * 8 + group;
#pragma unroll
            for (int c = 0; c < 3; c++) {
                redv[w4][rowl][c] = tv[r][c];
                redi[w4][rowl][c] = ti[r][c];
            }
        }
    }
    __syncthreads();

    if (tid < 64) {
        int rowg = i0 + tid;
        if (rowg < NPGc) {
            float fv[3]; int fi[3];
#pragma unroll
            for (int c = 0; c < 3; c++) { fv[c] = redv[0][tid][c]; fi[c] = redi[0][tid][c]; }
#pragma unroll
            for (int w = 1; w < 4; w++)
#pragma unroll
                for (int c = 0; c < 3; c++) tk3(redv[w][tid][c], redi[w][tid][c], fv, fi);
            int* o = g_knn + (size_t)(goff + rowg) * 3;
            o[0] = fi[0]; o[1] = fi[1]; o[2] = fi[2];
        }
    }
}

// ---------------- gathers with fused stats + bf16 output ----------------
__device__ __forceinline__ void gather_epi(float4 acc, int tid, int blk,
                                           __nv_bfloat16* obuf, size_t obase) {
    __shared__ float sh1[1024], sh2[1024];
    uint2 p;
    p.x = packbf2(acc.x, acc.y);
    p.y = packbf2(acc.z, acc.w);
    *(uint2*)(obuf + obase) = p;
    *(float4*)&sh1[tid * 4] = acc;
    *(float4*)&sh2[tid * 4] = make_float4(acc.x * acc.x, acc.y * acc.y,
                                          acc.z * acc.z, acc.w * acc.w);
    __syncthreads();
    if (tid < 64) {
        float4 s1 = make_float4(0.f, 0.f, 0.f, 0.f);
        float4 s2 = make_float4(0.f, 0.f, 0.f, 0.f);
#pragma unroll
        for (int nd = 0; nd < 4; nd++) {
            float4 a = *(float4*)&sh1[(nd * 64 + tid) * 4];
            float4 b = *(float4*)&sh2[(nd * 64 + tid) * 4];
            s1.x += a.x; s1.y += a.y; s1.z += a.z; s1.w += a.w;
            s2.x += b.x; s2.y += b.y; s2.z += b.z; s2.w += b.w;
        }
        int g = (blk * 4) / NPGc;
        int base = g * 256 + tid * 4;
        atomicAdd(&g_s1[base + 0], s1.x); atomicAdd(&g_s1[base + 1], s1.y);
        atomicAdd(&g_s1[base + 2], s1.z); atomicAdd(&g_s1[base + 3], s1.w);
        atomicAdd(&g_s2[base + 0], s2.x); atomicAdd(&g_s2[base + 1], s2.y);
        atomicAdd(&g_s2[base + 2], s2.z); atomicAdd(&g_s2[base + 3], s2.w);
    }
}

__global__ __launch_bounds__(256) void conv_gather_k(const float* __restrict__ bias) {
    int tid = threadIdx.x;
    int t = blockIdx.x * 256 + tid;
    int n = t >> 6, q = t & 63;
    float d0 = g_dinv[n];
    float co = d0 * d0;
    float4 a = bf4tof4(*(const uint2*)(g_mb + (size_t)n * 256 + q * 4));
    float4 bv = ((const float4*)bias)[q];
    float4 acc = make_float4(a.x * co + bv.x, a.y * co + bv.y,
                             a.z * co + bv.z, a.w * co + bv.w);
    int off = g_off[n], cnt = g_cnt[n];
    for (int j = 0; j < cnt; j++) {
        int s = g_esrc[off + j];
        float cf = g_ecoef[off + j];
        float4 v = bf4tof4(*(const uint2*)(g_mb + (size_t)s * 256 + q * 4));
        acc.x += v.x * cf; acc.y += v.y * cf; acc.z += v.z * cf; acc.w += v.w * cf;
    }
    gather_epi(acc, tid, blockIdx.x, g_cb, (size_t)n * 256 + q * 4);
}

__global__ __launch_bounds__(256) void knn_agg_k(const float* __restrict__ bias) {
    int tid = threadIdx.x;
    int t = blockIdx.x * 256 + tid;
    int n = t >> 6, q = t & 63;
    int i0 = g_knn[n * 3 + 0], i1 = g_knn[n * 3 + 1], i2 = g_knn[n * 3 + 2];
    float4 a = bf4tof4(*(const uint2*)(g_mb + (size_t)n * 256 + q * 4));
    float4 b = bf4tof4(*(const uint2*)(g_mb + (size_t)i0 * 256 + q * 4));
    float4 c = bf4tof4(*(const uint2*)(g_mb + (size_t)i1 * 256 + q * 4));
    float4 d = bf4tof4(*(const uint2*)(g_mb + (size_t)i2 * 256 + q * 4));
    float4 bv = ((const float4*)bias)[q];
    float4 acc = make_float4(0.25f * (a.x + b.x + c.x + d.x) + bv.x,
                             0.25f * (a.y + b.y + c.y + d.y) + bv.y,
                             0.25f * (a.z + b.z + c.z + d.z) + bv.z,
                             0.25f * (a.w + b.w + c.w + d.w) + bv.w);
    gather_epi(acc, tid, blockIdx.x, g_fbuf, (size_t)n * 256 + q * 4);
}

// ---------------- finalize norm params (self-zeroing stats) ----------------
__global__ void finalize_k(const float* __restrict__ w, const float* __restrict__ b,
                           const float* __restrict__ ms,
                           float* __restrict__ alpha, float* __restrict__ beta) {
    int i = blockIdx.x * blockDim.x + threadIdx.x;
    if (i >= Gg * Hh) return;
    int cc = i & 255;
    float mean = g_s1[i] * (1.0f / NPGc);
    float ex2 = g_s2[i] * (1.0f / NPGc);
    float m = ms[cc];
    float var = ex2 - mean * mean * m * (2.0f - m);
    float a = w[cc] * rsqrtf(var + 1e-5f);
    alpha[i] = a;
    beta[i] = b[cc] - a * m * mean;
    g_s1[i] = 0.0f;
    g_s2[i] = 0.0f;
}

// ---------------- launch ----------------
extern "C" void kernel_launch(void* const* d_in, const int* in_sizes, int n_in,
                              void* d_out, int out_size) {
    const float* x       = (const float*)d_in[0];
    const int*   ei      = (const int*)d_in[1];
    const float* emb_W   = (const float*)d_in[3];
    const float* emb_b   = (const float*)d_in[4];
    const float* conv_W  = (const float*)d_in[5];
    const float* conv_b  = (const float*)d_in[6];
    const float* fconv_W = (const float*)d_in[7];
    const float* fconv_b = (const float*)d_in[8];
    const float* norm_w  = (const float*)d_in[9];
    const float* norm_b  = (const float*)d_in[10];
    const float* norm_ms = (const float*)d_in[11];
    const float* fnorm_w = (const float*)d_in[12];
    const float* fnorm_b = (const float*)d_in[13];
    const float* fnorm_ms= (const float*)d_in[14];
    const float* gate_W  = (const float*)d_in[15];
    const float* gate_b  = (const float*)d_in[16];
    float* out = (float*)d_out;

    const int* src = ei;
    const int* dst = ei + Ee;

    float *h, *ac, *bc, *af, *bf;
    __nv_bfloat16 *mb, *cb, *fb;
    uint32_t* wp;
    cudaGetSymbolAddress((void**)&h, g_h);
    cudaGetSymbolAddress((void**)&mb, g_mb);
    cudaGetSymbolAddress((void**)&cb, g_cb);
    cudaGetSymbolAddress((void**)&fb, g_fbuf);
    cudaGetSymbolAddress((void**)&wp, g_wpack);
    cudaGetSymbolAddress((void**)&ac, g_ac);
    cudaGetSymbolAddress((void**)&bc, g_bc);
    cudaGetSymbolAddress((void**)&af, g_af);
    cudaGetSymbolAddress((void**)&bf, g_bf);

    const int TPB = 256;
    const int MB = (Nn + 127) / 128;     // 391
    dim3 gemm_grid(2, MB);
    const int NBLK = (Nn + 255) / 256;   // 196
    const int WPB = (WSLOT + TPB - 1) / TPB;

    zerof_k<<<(Gg * Hh + TPB - 1) / TPB, TPB>>>(out, Gg * Hh);

    // pack weights
    wpack_k<<<WPB, TPB>>>(conv_W,              0);
    wpack_k<<<WPB, TPB>>>(conv_W + Hh * Hh,    1);
    wpack_k<<<WPB, TPB>>>(fconv_W,             2);
    wpack_k<<<WPB, TPB>>>(fconv_W + Hh * Hh,   3);
    wpack_k<<<WPB, TPB>>>(gate_W,              4);
    wpack_k<<<WPB, TPB>>>(gate_W + Hh * Hh,    5);
    embpack_k<<<(INf * Hh + TPB - 1) / TPB, TPB>>>(emb_W);

    // degrees + CSR
    cnt_zero_k<<<NBLK, TPB>>>();
    cnt_count_k<<<(Ee + TPB - 1) / TPB, TPB>>>(dst);
    dinv_k<<<NBLK, TPB>>>();
    scan1_k<<<NBLK, 256>>>();
    scan2_k<<<1, 256>>>(NBLK);
    scan3_k<<<NBLK, TPB>>>();
    fill_k<<<(Ee + TPB - 1) / TPB, TPB>>>(src, dst);

    // h = x @ emb_W + b  (tf32x3 tensor cores)
    emb_mma_k<<<gemm_grid, TPB>>>(x, emb_b, h);

    // cosine knn
    rownorm_k<<<Nn, 64>>>();
    simtopk_mma_k<<<dim3(8, Gg), TPB>>>();

    float pool_w[2] = {1.0f, 2.0f};   // gf = pool(x0) + 2*pool(x1)  (all_x[i-1] quirk)

    for (int li = 0; li < 2; li++) {
        // conv branch
        mmabf16_k<0, 0><<<gemm_grid, TPB>>>(h, wp + (size_t)li * WSLOT, mb, nullptr, nullptr);
        conv_gather_k<<<(Nn * 64) / 256, TPB>>>(conv_b + li * Hh);
        finalize_k<<<(Gg * Hh + TPB - 1) / TPB, TPB>>>(norm_w + li * Hh, norm_b + li * Hh,
                                                       norm_ms + li * Hh, ac, bc);
        // feature branch (A = norm_c(cb) fused)
        mmabf16_k<1, 1><<<gemm_grid, TPB>>>(cb, wp + (size_t)(2 + li) * WSLOT, mb, ac, bc);
        knn_agg_k<<<(Nn * 64) / 256, TPB>>>(fconv_b + li * Hh);
        finalize_k<<<(Gg * Hh + TPB - 1) / TPB, TPB>>>(fnorm_w + li * Hh, fnorm_b + li * Hh,
                                                       fnorm_ms + li * Hh, af, bf);
        // merged gate (K=512) + blend + residual + fused pool -> h, out
        gate_k<<<gemm_grid, TPB>>>(wp + (size_t)4 * WSLOT, gate_b, h, out,
                                   pool_w[li] * (1.0f / NPGc));
    }
    (void)in_sizes; (void)n_in; (void)out_size;
}

// round 14
// speedup vs baseline: 1.1202x; 1.1202x over previous
#include <cuda_runtime.h>
#include <cuda_bf16.h>
#include <math.h>
#include <stdint.h>

#define Nn   50000
#define Gg   100
#define NPGc 500
#define INf  128
#define Hh   256
#define Ee   800000
#define SPLIT 10
#define RPS   50
#define WSLOT (128 * 256)

// ---------------- scratch ----------------
__device__ float g_h   [Nn * Hh];
__device__ float g_xh  [Nn * Hh];
__device__ float g_xl  [Nn * Hh];
__device__ __nv_bfloat16 g_mb [Nn * Hh];
__device__ __nv_bfloat16 g_cb [Nn * Hh];
__device__ __nv_bfloat16 g_fbuf[Nn * Hh];
__device__ int   g_knn [Nn * 3];
__device__ int   g_cnt [Nn];
__device__ float g_dinv[Nn];
__device__ int   g_scan[Nn];
__device__ int   g_off [Nn];
__device__ int   g_fill[Nn];
__device__ int   g_bsum[256];
__device__ int   g_bbase[256];
__device__ int   g_esrc[Ee];
__device__ float g_ecoef[Ee];
__device__ float g_s1  [Gg * Hh];    // zero-init; finalize re-zeroes after read
__device__ float g_s2  [Gg * Hh];
__device__ float g_ac  [Gg * Hh];
__device__ float g_bc  [Gg * Hh];
__device__ float g_af  [Gg * Hh];
__device__ float g_bf  [Gg * Hh];
__device__ uint32_t g_wpack[6][WSLOT];
__device__ float g_ewh[INf * Hh];
__device__ float g_ewl[INf * Hh];

// ---------------- helpers ----------------
__device__ __forceinline__ uint32_t f2tf(float f) {
    uint32_t u;
    asm("cvt.rna.tf32.f32 %0, %1;" : "=r"(u) : "f"(f));
    return u;
}
__device__ __forceinline__ uint32_t packbf2(float lo, float hi) {
    __nv_bfloat162 p = __floats2bfloat162_rn(lo, hi);
    return *(uint32_t*)&p;
}
__device__ __forceinline__ void mma16(float* c, const uint32_t* a, const uint32_t* b) {
    asm volatile(
        "mma.sync.aligned.m16n8k16.row.col.f32.bf16.bf16.f32 "
        "{%0,%1,%2,%3}, {%4,%5,%6,%7}, {%8,%9}, {%0,%1,%2,%3};"
        : "+f"(c[0]), "+f"(c[1]), "+f"(c[2]), "+f"(c[3])
        : "r"(a[0]), "r"(a[1]), "r"(a[2]), "r"(a[3]), "r"(b[0]), "r"(b[1]));
}
__device__ __forceinline__ void mma8(float* c, const uint32_t* a, const uint32_t* b) {
    asm volatile(
        "mma.sync.aligned.m16n8k8.row.col.f32.tf32.tf32.f32 "
        "{%0,%1,%2,%3}, {%4,%5,%6,%7}, {%8,%9}, {%0,%1,%2,%3};"
        : "+f"(c[0]), "+f"(c[1]), "+f"(c[2]), "+f"(c[3])
        : "r"(a[0]), "r"(a[1]), "r"(a[2]), "r"(a[3]), "r"(b[0]), "r"(b[1]));
}
__device__ __forceinline__ float4 bf4tof4(uint2 u) {
    __nv_bfloat162 a = *(__nv_bfloat162*)&u.x;
    __nv_bfloat162 b = *(__nv_bfloat162*)&u.y;
    return make_float4(__bfloat162float(a.x), __bfloat162float(a.y),
                       __bfloat162float(b.x), __bfloat162float(b.y));
}

// ---------------- small utility kernels ----------------
__global__ void zerof_k(float* p, int n) {
    int i = blockIdx.x * blockDim.x + threadIdx.x;
    if (i < n) p[i] = 0.0f;
}
__global__ void cnt_zero_k() {
    int i = blockIdx.x * blockDim.x + threadIdx.x;
    if (i < Nn) g_cnt[i] = 0;
}
__global__ void cnt_count_k(const int* __restrict__ dst) {
    int e = blockIdx.x * blockDim.x + threadIdx.x;
    if (e < Ee) atomicAdd(&g_cnt[dst[e]], 1);
}
__global__ void dinv_k() {
    int i = blockIdx.x * blockDim.x + threadIdx.x;
    if (i < Nn) g_dinv[i] = rsqrtf((float)g_cnt[i] + 1.0f);
}
__global__ void wpack_k(const float* __restrict__ W, int slot) {
    int i = blockIdx.x * blockDim.x + threadIdx.x;
    if (i >= WSLOT) return;
    int kk = i >> 8, n = i & 255;
    __nv_bfloat162 p = __floats2bfloat162_rn(W[(2 * kk) * 256 + n], W[(2 * kk + 1) * 256 + n]);
    g_wpack[slot][i] = *(uint32_t*)&p;
}
__global__ void embpack_k(const float* __restrict__ W) {
    int i = blockIdx.x * blockDim.x + threadIdx.x;
    if (i >= INf * Hh) return;
    float w = W[i];
    float h = __uint_as_float(f2tf(w));
    g_ewh[i] = h;
    g_ewl[i] = __uint_as_float(f2tf(w - h));
}

// ---------------- CSR build ----------------
__global__ void scan1_k() {
    __shared__ int sh[256];
    int i = blockIdx.x * 256 + threadIdx.x;
    int v = (i < Nn) ? g_cnt[i] : 0;
    sh[threadIdx.x] = v;
    __syncthreads();
    for (int off = 1; off < 256; off <<= 1) {
        int t = (threadIdx.x >= off) ? sh[threadIdx.x - off] : 0;
        __syncthreads();
        sh[threadIdx.x] += t;
        __syncthreads();
    }
    if (i < Nn) g_scan[i] = sh[threadIdx.x];
    if (threadIdx.x == 255) g_bsum[blockIdx.x] = sh[255];
}
__global__ void scan2_k(int nblk) {
    __shared__ int sh[256];
    int b = threadIdx.x;
    int v = (b < nblk) ? g_bsum[b] : 0;
    sh[b] = v;
    __syncthreads();
    for (int off = 1; off < 256; off <<= 1) {
        int t = (b >= off) ? sh[b - off] : 0;
        __syncthreads();
        sh[b] += t;
        __syncthreads();
    }
    if (b < nblk) g_bbase[b] = sh[b] - v;
}
__global__ void scan3_k() {
    int i = blockIdx.x * blockDim.x + threadIdx.x;
    if (i < Nn) {
        int off = g_scan[i] - g_cnt[i] + g_bbase[i >> 8];
        g_off[i] = off;
        g_fill[i] = off;
    }
}
__global__ void fill_k(const int* __restrict__ src, const int* __restrict__ dst) {
    int e = blockIdx.x * blockDim.x + threadIdx.x;
    if (e >= Ee) return;
    int s = src[e], d = dst[e];
    int p = atomicAdd(&g_fill[d], 1);
    g_esrc[p] = s;
    g_ecoef[p] = g_dinv[s] * g_dinv[d];
}

// ---------------- emb GEMM: tf32x3 tensor cores, h = x @ emb_W + b ----------------
__global__ __launch_bounds__(256, 2) void emb_mma_k(
    const float* __restrict__ A, const float* __restrict__ bias, float* __restrict__ out)
{
    __shared__ uint32_t AsH[128][20], AsL[128][20];
    __shared__ uint32_t BsH[16][136], BsL[16][136];

    int tid = threadIdx.x;
    int wid = tid >> 5, lane = tid & 31;
    int m0 = blockIdx.y * 128, n0 = blockIdx.x * 128;
    int wm = (wid & 3) * 32, wn = (wid >> 2) * 64;
    int group = lane >> 2, tig = lane & 3;

    float acc[2][8][4];
#pragma unroll
    for (int mt = 0; mt < 2; mt++)
#pragma unroll
        for (int nt = 0; nt < 8; nt++)
#pragma unroll
            for (int q = 0; q < 4; q++) acc[mt][nt][q] = 0.0f;

    int arow = tid >> 1, acK = (tid & 1) * 8;
    int bkr = tid >> 4, bn8 = (tid & 15) * 8;
    bool vA = (m0 + arow) < Nn;
    float4 z4 = make_float4(0.f, 0.f, 0.f, 0.f);

    for (int kt = 0; kt < 8; kt++) {
        int k0 = kt * 16;
        float4 a0 = vA ? *(const float4*)(A + (size_t)(m0 + arow) * INf + k0 + acK) : z4;
        float4 a1 = vA ? *(const float4*)(A + (size_t)(m0 + arow) * INf + k0 + acK + 4) : z4;
        float av[8] = {a0.x, a0.y, a0.z, a0.w, a1.x, a1.y, a1.z, a1.w};
#pragma unroll
        for (int j = 0; j < 8; j++) {
            uint32_t hb = f2tf(av[j]);
            AsH[arow][acK + j] = hb;
            AsL[arow][acK + j] = f2tf(av[j] - __uint_as_float(hb));
        }
        const float* bh = g_ewh + (size_t)(k0 + bkr) * 256 + n0 + bn8;
        const float* bl = g_ewl + (size_t)(k0 + bkr) * 256 + n0 + bn8;
        *(float4*)&BsH[bkr][bn8]     = *(const float4*)(bh);
        *(float4*)&BsH[bkr][bn8 + 4] = *(const float4*)(bh + 4);
        *(float4*)&BsL[bkr][bn8]     = *(const float4*)(bl);
        *(float4*)&BsL[bkr][bn8 + 4] = *(const float4*)(bl + 4);
        __syncthreads();

#pragma unroll
        for (int ks = 0; ks < 2; ks++) {
            int kb = ks * 8;
            uint32_t ah[2][4], al[2][4];
#pragma unroll
            for (int mt = 0; mt < 2; mt++) {
                int r = wm + mt * 16 + group;
                ah[mt][0] = AsH[r][kb + tig];     ah[mt][1] = AsH[r + 8][kb + tig];
                ah[mt][2] = AsH[r][kb + tig + 4]; ah[mt][3] = AsH[r + 8][kb + tig + 4];
                al[mt][0] = AsL[r][kb + tig];     al[mt][1] = AsL[r + 8][kb + tig];
                al[mt][2] = AsL[r][kb + tig + 4]; al[mt][3] = AsL[r + 8][kb + tig + 4];
            }
            uint32_t bh2[8][2], bl2[8][2];
#pragma unroll
            for (int nt = 0; nt < 8; nt++) {
                int cc = wn + nt * 8 + group;
                bh2[nt][0] = BsH[kb + tig][cc]; bh2[nt][1] = BsH[kb + tig + 4][cc];
                bl2[nt][0] = BsL[kb + tig][cc]; bl2[nt][1] = BsL[kb + tig + 4][cc];
            }
#pragma unroll
            for (int mt = 0; mt < 2; mt++)
#pragma unroll
                for (int nt = 0; nt < 8; nt++) {
                    mma8(acc[mt][nt], ah[mt], bh2[nt]);
                    mma8(acc[mt][nt], ah[mt], bl2[nt]);
                    mma8(acc[mt][nt], al[mt], bh2[nt]);
                }
        }
        __syncthreads();
    }

#pragma unroll
    for (int mt = 0; mt < 2; mt++)
#pragma unroll
        for (int half = 0; half < 2; half++) {
            int row = m0 + wm + mt * 16 + group + half * 8;
            if (row >= Nn) continue;
#pragma unroll
            for (int nt = 0; nt < 8; nt++) {
                int col = n0 + wn + nt * 8 + 2 * tig;
                size_t base = (size_t)row * 256 + col;
                out[base]     = acc[mt][nt][half * 2 + 0] + bias[col];
                out[base + 1] = acc[mt][nt][half * 2 + 1] + bias[col + 1];
            }
        }
}

// ---------------- bf16 mma GEMM -> mb (bf16). NORMA: fused graphnorm+leaky on A ----------------
template <int NORMA, int ABF>
__global__ __launch_bounds__(256, 2) void mmabf16_k(
    const void* __restrict__ Araw, const uint32_t* __restrict__ Bp,
    __nv_bfloat16* __restrict__ bout,
    const float* __restrict__ nAa, const float* __restrict__ nAb)
{
    __shared__ uint32_t As[128][20];
    __shared__ uint32_t Bs[16][136];

    int tid = threadIdx.x;
    int wid = tid >> 5, lane = tid & 31;
    int m0 = blockIdx.y * 128, n0 = blockIdx.x * 128;
    int wm = (wid & 3) * 32, wn = (wid >> 2) * 64;
    int group = lane >> 2, tig = lane & 3;

    float acc[2][8][4];
#pragma unroll
    for (int mt = 0; mt < 2; mt++)
#pragma unroll
        for (int nt = 0; nt < 8; nt++)
#pragma unroll
            for (int q = 0; q < 4; q++) acc[mt][nt][q] = 0.0f;

    int arow = tid >> 3, acK = (tid & 7) * 4;
    int bkr = tid >> 4, bn8 = (tid & 15) * 8;

    bool vAi[4];
    int ggA[4];
#pragma unroll
    for (int i = 0; i < 4; i++) {
        int r = m0 + arow + 32 * i;
        vAi[i] = r < Nn;
        ggA[i] = vAi[i] ? (r / NPGc) : 0;
    }

    const float* Af = (const float*)Araw;
    const __nv_bfloat16* Ab = (const __nv_bfloat16*)Araw;
    float4 paf[4];
    uint2 pab[4];
    uint4 pb[2];
    float4 z4 = make_float4(0.f, 0.f, 0.f, 0.f);
    uint2 z2 = make_uint2(0, 0);

#pragma unroll
    for (int i = 0; i < 4; i++) {
        int r = m0 + arow + 32 * i;
        if (ABF) pab[i] = vAi[i] ? *(const uint2*)(Ab + (size_t)r * 256 + acK) : z2;
        else     paf[i] = vAi[i] ? *(const float4*)(Af + (size_t)r * 256 + acK) : z4;
    }
#pragma unroll
    for (int j = 0; j < 2; j++)
        pb[j] = *(const uint4*)(Bp + (size_t)bkr * 256 + n0 + bn8 + 4 * j);

    for (int kt = 0; kt < 8; kt++) {
#pragma unroll
        for (int i = 0; i < 4; i++) {
            float4 w = ABF ? bf4tof4(pab[i]) : paf[i];
            if (NORMA) {
                if (vAi[i]) {
                    float4 a4 = *(const float4*)(nAa + ggA[i] * 256 + kt * 32 + acK);
                    float4 b4 = *(const float4*)(nAb + ggA[i] * 256 + kt * 32 + acK);
                    w.x = fmaf(w.x, a4.x, b4.x); w.x = w.x > 0.f ? w.x : 0.01f * w.x;
                    w.y = fmaf(w.y, a4.y, b4.y); w.y = w.y > 0.f ? w.y : 0.01f * w.y;
                    w.z = fmaf(w.z, a4.z, b4.z); w.z = w.z > 0.f ? w.z : 0.01f * w.z;
                    w.w = fmaf(w.w, a4.w, b4.w); w.w = w.w > 0.f ? w.w : 0.01f * w.w;
                }
            }
            As[arow + 32 * i][(acK >> 1) + 0] = packbf2(w.x, w.y);
            As[arow + 32 * i][(acK >> 1) + 1] = packbf2(w.z, w.w);
        }
#pragma unroll
        for (int j = 0; j < 2; j++)
            *(uint4*)&Bs[bkr][bn8 + 4 * j] = pb[j];
        __syncthreads();

        if (kt < 7) {
            int k0 = (kt + 1) * 32;
#pragma unroll
            for (int i = 0; i < 4; i++) {
                int r = m0 + arow + 32 * i;
                if (ABF) pab[i] = vAi[i] ? *(const uint2*)(Ab + (size_t)r * 256 + k0 + acK) : z2;
                else     paf[i] = vAi[i] ? *(const float4*)(Af + (size_t)r * 256 + k0 + acK) : z4;
            }
#pragma unroll
            for (int j = 0; j < 2; j++)
                pb[j] = *(const uint4*)(Bp + (size_t)((k0 >> 1) + bkr) * 256 + n0 + bn8 + 4 * j);
        }

#pragma unroll
        for (int s = 0; s < 2; s++) {
            uint32_t afr[2][4];
#pragma unroll
            for (int mt = 0; mt < 2; mt++) {
                int r = wm + mt * 16 + group;
                afr[mt][0] = As[r][s * 8 + tig];
                afr[mt][1] = As[r + 8][s * 8 + tig];
                afr[mt][2] = As[r][s * 8 + tig + 4];
                afr[mt][3] = As[r + 8][s * 8 + tig + 4];
            }
            uint32_t bfr[8][2];
#pragma unroll
            for (int nt = 0; nt < 8; nt++) {
                int cc = wn + nt * 8 + group;
                bfr[nt][0] = Bs[s * 8 + tig][cc];
                bfr[nt][1] = Bs[s * 8 + tig + 4][cc];
            }
#pragma unroll
            for (int mt = 0; mt < 2; mt++)
#pragma unroll
                for (int nt = 0; nt < 8; nt++) mma16(acc[mt][nt], afr[mt], bfr[nt]);
        }
        __syncthreads();
    }

#pragma unroll
    for (int mt = 0; mt < 2; mt++)
#pragma unroll
        for (int half = 0; half < 2; half++) {
            int row = m0 + wm + mt * 16 + group + half * 8;
            if (row >= Nn) continue;
#pragma unroll
            for (int nt = 0; nt < 8; nt++) {
                int col = n0 + wn + nt * 8 + 2 * tig;
                size_t base = (size_t)row * 256 + col;
                __nv_bfloat162 p = __floats2bfloat162_rn(acc[mt][nt][half * 2 + 0],
                                                         acc[mt][nt][half * 2 + 1]);
                *(__nv_bfloat162*)(bout + base) = p;
            }
        }
}

// ---------------- merged gate GEMM: K=512 + blend + residual ----------------
__global__ __launch_bounds__(256, 2) void gate_k(
    const uint32_t* __restrict__ Bp, const float* __restrict__ gate_b,
    float* __restrict__ h)
{
    __shared__ uint32_t As[128][20];
    __shared__ uint32_t Bs[16][136];

    int tid = threadIdx.x;
    int wid = tid >> 5, lane = tid & 31;
    int m0 = blockIdx.y * 128, n0 = blockIdx.x * 128;
    int wm = (wid & 3) * 32, wn = (wid >> 2) * 64;
    int group = lane >> 2, tig = lane & 3;

    float acc[2][8][4];
#pragma unroll
    for (int mt = 0; mt < 2; mt++)
#pragma unroll
        for (int nt = 0; nt < 8; nt++)
#pragma unroll
            for (int q = 0; q < 4; q++) acc[mt][nt][q] = 0.0f;

    int arow = tid >> 3, acK = (tid & 7) * 4;
    int bkr = tid >> 4, bn8 = (tid & 15) * 8;

    bool vAi[4];
    int ggA[4];
#pragma unroll
    for (int i = 0; i < 4; i++) {
        int r = m0 + arow + 32 * i;
        vAi[i] = r < Nn;
        ggA[i] = vAi[i] ? (r / NPGc) : 0;
    }

    uint2 pab[4];
    uint4 pb[2];
    uint2 z2 = make_uint2(0, 0);

#pragma unroll
    for (int i = 0; i < 4; i++) {
        int r = m0 + arow + 32 * i;
        pab[i] = vAi[i] ? *(const uint2*)(g_cb + (size_t)r * 256 + acK) : z2;
    }
#pragma unroll
    for (int j = 0; j < 2; j++)
        pb[j] = *(const uint4*)(Bp + (size_t)bkr * 256 + n0 + bn8 + 4 * j);

    for (int kt = 0; kt < 16; kt++) {
        int khalf = kt >> 3;                 // 0: c-branch, 1: f-branch
        int koff = (kt & 7) * 32;
        const float* na = khalf ? g_af : g_ac;
        const float* nb = khalf ? g_bf : g_bc;
#pragma unroll
        for (int i = 0; i < 4; i++) {
            float4 w = bf4tof4(pab[i]);
            if (vAi[i]) {
                float4 a4 = *(const float4*)(na + ggA[i] * 256 + koff + acK);
                float4 b4 = *(const float4*)(nb + ggA[i] * 256 + koff + acK);
                w.x = fmaf(w.x, a4.x, b4.x); w.x = w.x > 0.f ? w.x : 0.01f * w.x;
                w.y = fmaf(w.y, a4.y, b4.y); w.y = w.y > 0.f ? w.y : 0.01f * w.y;
                w.z = fmaf(w.z, a4.z, b4.z); w.z = w.z > 0.f ? w.z : 0.01f * w.z;
                w.w = fmaf(w.w, a4.w, b4.w); w.w = w.w > 0.f ? w.w : 0.01f * w.w;
            }
            As[arow + 32 * i][(acK >> 1) + 0] = packbf2(w.x, w.y);
            As[arow + 32 * i][(acK >> 1) + 1] = packbf2(w.z, w.w);
        }
#pragma unroll
        for (int j = 0; j < 2; j++)
            *(uint4*)&Bs[bkr][bn8 + 4 * j] = pb[j];
        __syncthreads();

        if (kt < 15) {
            int nk = kt + 1;
            const __nv_bfloat16* Asrc = (nk < 8) ? g_cb : g_fbuf;
            int nkoff = (nk & 7) * 32;
#pragma unroll
            for (int i = 0; i < 4; i++) {
                int r = m0 + arow + 32 * i;
                pab[i] = vAi[i] ? *(const uint2*)(Asrc + (size_t)r * 256 + nkoff + acK) : z2;
            }
#pragma unroll
            for (int j = 0; j < 2; j++)
                pb[j] = *(const uint4*)(Bp + (size_t)((nk * 16) + bkr) * 256 + n0 + bn8 + 4 * j);
        }

#pragma unroll
        for (int s = 0; s < 2; s++) {
            uint32_t afr[2][4];
#pragma unroll
            for (int mt = 0; mt < 2; mt++) {
                int r = wm + mt * 16 + group;
                afr[mt][0] = As[r][s * 8 + tig];
                afr[mt][1] = As[r + 8][s * 8 + tig];
                afr[mt][2] = As[r][s * 8 + tig + 4];
                afr[mt][3] = As[r + 8][s * 8 + tig + 4];
            }
            uint32_t bfr[8][2];
#pragma unroll
            for (int nt = 0; nt < 8; nt++) {
                int cc = wn + nt * 8 + group;
                bfr[nt][0] = Bs[s * 8 + tig][cc];
                bfr[nt][1] = Bs[s * 8 + tig + 4][cc];
            }
#pragma unroll
            for (int mt = 0; mt < 2; mt++)
#pragma unroll
                for (int nt = 0; nt < 8; nt++) mma16(acc[mt][nt], afr[mt], bfr[nt]);
        }
        __syncthreads();
    }

    // epilogue: g = sigmoid(acc + gate_b); h = g*leaky(norm_c(c)) + (1-g)*leaky(norm_f(f)) + h
#pragma unroll
    for (int mt = 0; mt < 2; mt++)
#pragma unroll
        for (int half = 0; half < 2; half++) {
            int row = m0 + wm + mt * 16 + group + half * 8;
            if (row >= Nn) continue;
            int gg = row / NPGc;
#pragma unroll
            for (int nt = 0; nt < 8; nt++) {
                int col = n0 + wn + nt * 8 + 2 * tig;
                size_t base = (size_t)row * 256 + col;
                int cb2 = gg * 256 + col;
                float s0 = acc[mt][nt][half * 2 + 0] + gate_b[col];
                float s1 = acc[mt][nt][half * 2 + 1] + gate_b[col + 1];
                float gt0 = 1.0f / (1.0f + expf(-s0));
                float gt1 = 1.0f / (1.0f + expf(-s1));
                __nv_bfloat162 cv = *(const __nv_bfloat162*)(g_cb + base);
                __nv_bfloat162 fv = *(const __nv_bfloat162*)(g_fbuf + base);
                float c0 = fmaf(__bfloat162float(cv.x), g_ac[cb2],     g_bc[cb2]);
                float c1 = fmaf(__bfloat162float(cv.y), g_ac[cb2 + 1], g_bc[cb2 + 1]);
                c0 = c0 > 0.f ? c0 : 0.01f * c0;
                c1 = c1 > 0.f ? c1 : 0.01f * c1;
                float f0 = fmaf(__bfloat162float(fv.x), g_af[cb2],     g_bf[cb2]);
                float f1 = fmaf(__bfloat162float(fv.y), g_af[cb2 + 1], g_bf[cb2 + 1]);
                f0 = f0 > 0.f ? f0 : 0.01f * f0;
                f1 = f1 > 0.f ? f1 : 0.01f * f1;
                h[base]     = gt0 * c0 + (1.0f - gt0) * f0 + h[base];
                h[base + 1] = gt1 * c1 + (1.0f - gt1) * f1 + h[base + 1];
            }
        }
}

// ---------------- row normalize + tf32 hi/lo split ----------------
__global__ void rownorm_k() {
    int row = blockIdx.x;
    int t = threadIdx.x;
    float4 v = *(const float4*)(g_h + (size_t)row * Hh + t * 4);
    float s = v.x * v.x + v.y * v.y + v.z * v.z + v.w * v.w;
    __shared__ float sh[64];
    sh[t] = s;
    __syncthreads();
    for (int off = 32; off > 0; off >>= 1) {
        if (t < off) sh[t] += sh[t + off];
        __syncthreads();
    }
    float inv = 1.0f / (sqrtf(sh[0]) + 1e-12f);
    float n0 = v.x * inv, n1 = v.y * inv, n2 = v.z * inv, n3 = v.w * inv;
    float h0 = __uint_as_float(f2tf(n0));
    float h1 = __uint_as_float(f2tf(n1));
    float h2 = __uint_as_float(f2tf(n2));
    float h3 = __uint_as_float(f2tf(n3));
    *(float4*)(g_xh + (size_t)row * Hh + t * 4) = make_float4(h0, h1, h2, h3);
    *(float4*)(g_xl + (size_t)row * Hh + t * 4) =
        make_float4(__uint_as_float(f2tf(n0 - h0)), __uint_as_float(f2tf(n1 - h1)),
                    __uint_as_float(f2tf(n2 - h2)), __uint_as_float(f2tf(n3 - h3)));
}

// ---------------- top-3 insert ----------------
__device__ __forceinline__ void tk3(float v, int id, float* tv, int* ti) {
    if (v > tv[0] || (v == tv[0] && id < ti[0])) {
        tv[2] = tv[1]; ti[2] = ti[1];
        tv[1] = tv[0]; ti[1] = ti[0];
        tv[0] = v;     ti[0] = id;
    } else if (v > tv[1] || (v == tv[1] && id < ti[1])) {
        tv[2] = tv[1]; ti[2] = ti[1];
        tv[1] = v;     ti[1] = id;
    } else if (v > tv[2] || (v == tv[2] && id < ti[2])) {
        tv[2] = v;     ti[2] = id;
    }
}

// ---------------- fused 3xTF32 sim + top-3 ----------------
__global__ __launch_bounds__(256, 2) void simtopk_mma_k() {
    int g = blockIdx.y;
    int i0 = blockIdx.x * 64;
    const float* XH = g_xh + (size_t)g * NPGc * Hh;
    const float* XL = g_xl + (size_t)g * NPGc * Hh;
    int goff = g * NPGc;

    __shared__ uint32_t Ah[64][20], Al[64][20], Bh[128][20], Bl[128][20];
    __shared__ float redv[4][64][3];
    __shared__ int   redi[4][64][3];

    int tid = threadIdx.x;
    int wid = tid >> 5, lane = tid & 31;
    int group = lane >> 2, tig = lane & 3;
    int wrow = (wid & 1) * 32, wcol = (wid >> 1) * 32;

    float tv[4][3];
    int ti[4][3];
#pragma unroll
    for (int r = 0; r < 4; r++)
#pragma unroll
        for (int c = 0; c < 3; c++) { tv[r][c] = -1e30f; ti[r][c] = 0x7fffffff; }

    int rA = tid >> 2, qA = (tid & 3) * 4;
    int rB = tid >> 1, qB = (tid & 1) * 8;
    bool vA = (i0 + rA) < NPGc;
    const float* ahp = XH + (size_t)(i0 + rA) * Hh + qA;
    const float* alp = XL + (size_t)(i0 + rA) * Hh + qA;
    float4 zh = make_float4(0.f, 0.f, 0.f, 0.f);

    for (int jt = 0; jt < 4; jt++) {
        int j0 = jt * 128;
        bool vB = (j0 + rB) < NPGc;
        const float* bhp = XH + (size_t)(j0 + rB) * Hh + qB;
        const float* blp = XL + (size_t)(j0 + rB) * Hh + qB;

        float acc[2][4][4];
#pragma unroll
        for (int mt = 0; mt < 2; mt++)
#pragma unroll
            for (int nt = 0; nt < 4; nt++)
#pragma unroll
                for (int q = 0; q < 4; q++) acc[mt][nt][q] = 0.0f;

        for (int kt = 0; kt < 16; kt++) {
            int k0 = kt * 16;
            float4 va_h = vA ? *(const float4*)(ahp + k0) : zh;
            float4 va_l = vA ? *(const float4*)(alp + k0) : zh;
            *(uint4*)&Ah[rA][qA] = *(uint4*)&va_h;
            *(uint4*)&Al[rA][qA] = *(uint4*)&va_l;
            float4 vb_h0 = vB ? *(const float4*)(bhp + k0) : zh;
            float4 vb_h1 = vB ? *(const float4*)(bhp + k0 + 4) : zh;
            float4 vb_l0 = vB ? *(const float4*)(blp + k0) : zh;
            float4 vb_l1 = vB ? *(const float4*)(blp + k0 + 4) : zh;
            *(uint4*)&Bh[rB][qB]     = *(uint4*)&vb_h0;
            *(uint4*)&Bh[rB][qB + 4] = *(uint4*)&vb_h1;
            *(uint4*)&Bl[rB][qB]     = *(uint4*)&vb_l0;
            *(uint4*)&Bl[rB][qB + 4] = *(uint4*)&vb_l1;
            __syncthreads();

#pragma unroll
            for (int ks = 0; ks < 2; ks++) {
                int kb = ks * 8;
                uint32_t ah[2][4], al[2][4];
#pragma unroll
                for (int mt = 0; mt < 2; mt++) {
                    int r = wrow + mt * 16 + group;
                    ah[mt][0] = Ah[r][kb + tig];     ah[mt][1] = Ah[r + 8][kb + tig];
                    ah[mt][2] = Ah[r][kb + tig + 4]; ah[mt][3] = Ah[r + 8][kb + tig + 4];
                    al[mt][0] = Al[r][kb + tig];     al[mt][1] = Al[r + 8][kb + tig];
                    al[mt][2] = Al[r][kb + tig + 4]; al[mt][3] = Al[r + 8][kb + tig + 4];
                }
                uint32_t bh[4][2], bl[4][2];
#pragma unroll
                for (int nt = 0; nt < 4; nt++) {
                    int cc = wcol + nt * 8 + group;
                    bh[nt][0] = Bh[cc][kb + tig]; bh[nt][1] = Bh[cc][kb + tig + 4];
                    bl[nt][0] = Bl[cc][kb + tig]; bl[nt][1] = Bl[cc][kb + tig + 4];
                }
#pragma unroll
                for (int mt = 0; mt < 2; mt++)
#pragma unroll
                    for (int nt = 0; nt < 4; nt++) {
                        mma8(acc[mt][nt], ah[mt], bh[nt]);
                        mma8(acc[mt][nt], ah[mt], bl[nt]);
                        mma8(acc[mt][nt], al[mt], bh[nt]);
                    }
            }
            __syncthreads();
        }

#pragma unroll
        for (int mt = 0; mt < 2; mt++)
#pragma unroll
            for (int nt = 0; nt < 4; nt++)
#pragma unroll
                for (int q = 0; q < 4; q++) {
                    int half = q >> 1, cbit = q & 1;
                    int col = j0 + wcol + nt * 8 + 2 * tig + cbit;
                    if (col < NPGc) {
                        int r = mt * 2 + half;
                        tk3(acc[mt][nt][q], goff + col, tv[r], ti[r]);
                    }
                }
    }

#pragma unroll
    for (int x = 1; x <= 2; x <<= 1) {
#pragma unroll
        for (int r = 0; r < 4; r++) {
            float ov[3]; int oi[3];
#pragma unroll
            for (int c = 0; c < 3; c++) {
                ov[c] = __shfl_xor_sync(0xffffffff, tv[r][c], x);
                oi[c] = __shfl_xor_sync(0xffffffff, ti[r][c], x);
            }
#pragma unroll
            for (int c = 0; c < 3; c++) tk3(ov[c], oi[c], tv[r], ti[r]);
        }
    }

    if (tig == 0) {
        int w4 = wid >> 1;
#pragma unroll
        for (int r = 0; r < 4; r++) {
            int mt = r >> 1, half = r & 1;
            int rowl = wrow + mt * 16 + half * 8 + group;
#pragma unroll
            for (int c = 0; c < 3; c++) {
                redv[w4][rowl][c] = tv[r][c];
                redi[w4][rowl][c] = ti[r][c];
            }
        }
    }
    __syncthreads();

    if (tid < 64) {
        int rowg = i0 + tid;
        if (rowg < NPGc) {
            float fv[3]; int fi[3];
#pragma unroll
            for (int c = 0; c < 3; c++) { fv[c] = redv[0][tid][c]; fi[c] = redi[0][tid][c]; }
#pragma unroll
            for (int w = 1; w < 4; w++)
#pragma unroll
                for (int c = 0; c < 3; c++) tk3(redv[w][tid][c], redi[w][tid][c], fv, fi);
            int* o = g_knn + (size_t)(goff + rowg) * 3;
            o[0] = fi[0]; o[1] = fi[1]; o[2] = fi[2];
        }
    }
}

// ---------------- gathers with fused stats + bf16 output ----------------
__device__ __forceinline__ void gather_epi(float4 acc, int tid, int blk,
                                           __nv_bfloat16* obuf, size_t obase) {
    __shared__ float sh1[1024], sh2[1024];
    uint2 p;
    p.x = packbf2(acc.x, acc.y);
    p.y = packbf2(acc.z, acc.w);
    *(uint2*)(obuf + obase) = p;
    *(float4*)&sh1[tid * 4] = acc;
    *(float4*)&sh2[tid * 4] = make_float4(acc.x * acc.x, acc.y * acc.y,
                                          acc.z * acc.z, acc.w * acc.w);
    __syncthreads();
    if (tid < 64) {
        float4 s1 = make_float4(0.f, 0.f, 0.f, 0.f);
        float4 s2 = make_float4(0.f, 0.f, 0.f, 0.f);
#pragma unroll
        for (int nd = 0; nd < 4; nd++) {
            float4 a = *(float4*)&sh1[(nd * 64 + tid) * 4];
            float4 b = *(float4*)&sh2[(nd * 64 + tid) * 4];
            s1.x += a.x; s1.y += a.y; s1.z += a.z; s1.w += a.w;
            s2.x += b.x; s2.y += b.y; s2.z += b.z; s2.w += b.w;
        }
        int g = (blk * 4) / NPGc;
        int base = g * 256 + tid * 4;
        atomicAdd(&g_s1[base + 0], s1.x); atomicAdd(&g_s1[base + 1], s1.y);
        atomicAdd(&g_s1[base + 2], s1.z); atomicAdd(&g_s1[base + 3], s1.w);
        atomicAdd(&g_s2[base + 0], s2.x); atomicAdd(&g_s2[base + 1], s2.y);
        atomicAdd(&g_s2[base + 2], s2.z); atomicAdd(&g_s2[base + 3], s2.w);
    }
}

__global__ __launch_bounds__(256) void conv_gather_k(const float* __restrict__ bias) {
    int tid = threadIdx.x;
    int t = blockIdx.x * 256 + tid;
    int n = t >> 6, q = t & 63;
    float d0 = g_dinv[n];
    float co = d0 * d0;
    float4 a = bf4tof4(*(const uint2*)(g_mb + (size_t)n * 256 + q * 4));
    float4 bv = ((const float4*)bias)[q];
    float4 acc = make_float4(a.x * co + bv.x, a.y * co + bv.y,
                             a.z * co + bv.z, a.w * co + bv.w);
    int off = g_off[n], cnt = g_cnt[n];
    for (int j = 0; j < cnt; j++) {
        int s = g_esrc[off + j];
        float cf = g_ecoef[off + j];
        float4 v = bf4tof4(*(const uint2*)(g_mb + (size_t)s * 256 + q * 4));
        acc.x += v.x * cf; acc.y += v.y * cf; acc.z += v.z * cf; acc.w += v.w * cf;
    }
    gather_epi(acc, tid, blockIdx.x, g_cb, (size_t)n * 256 + q * 4);
}

__global__ __launch_bounds__(256) void knn_agg_k(const float* __restrict__ bias) {
    int tid = threadIdx.x;
    int t = blockIdx.x * 256 + tid;
    int n = t >> 6, q = t & 63;
    int i0 = g_knn[n * 3 + 0], i1 = g_knn[n * 3 + 1], i2 = g_knn[n * 3 + 2];
    float4 a = bf4tof4(*(const uint2*)(g_mb + (size_t)n * 256 + q * 4));
    float4 b = bf4tof4(*(const uint2*)(g_mb + (size_t)i0 * 256 + q * 4));
    float4 c = bf4tof4(*(const uint2*)(g_mb + (size_t)i1 * 256 + q * 4));
    float4 d = bf4tof4(*(const uint2*)(g_mb + (size_t)i2 * 256 + q * 4));
    float4 bv = ((const float4*)bias)[q];
    float4 acc = make_float4(0.25f * (a.x + b.x + c.x + d.x) + bv.x,
                             0.25f * (a.y + b.y + c.y + d.y) + bv.y,
                             0.25f * (a.z + b.z + c.z + d.z) + bv.z,
                             0.25f * (a.w + b.w + c.w + d.w) + bv.w);
    gather_epi(acc, tid, blockIdx.x, g_fbuf, (size_t)n * 256 + q * 4);
}

// ---------------- finalize norm params (self-zeroing stats) ----------------
__global__ void finalize_k(const float* __restrict__ w, const float* __restrict__ b,
                           const float* __restrict__ ms,
                           float* __restrict__ alpha, float* __restrict__ beta) {
    int i = blockIdx.x * blockDim.x + threadIdx.x;
    if (i >= Gg * Hh) return;
    int cc = i & 255;
    float mean = g_s1[i] * (1.0f / NPGc);
    float ex2 = g_s2[i] * (1.0f / NPGc);
    float m = ms[cc];
    float var = ex2 - mean * mean * m * (2.0f - m);
    float a = w[cc] * rsqrtf(var + 1e-5f);
    alpha[i] = a;
    beta[i] = b[cc] - a * m * mean;
    g_s1[i] = 0.0f;
    g_s2[i] = 0.0f;
}

// ---------------- pooling ----------------
__global__ void pool_k(const float* __restrict__ buf, float* __restrict__ out, float wgt) {
    int b = blockIdx.x;
    int g = b / SPLIT, sp = b % SPLIT;
    int cc = threadIdx.x;
    int r0 = g * NPGc + sp * RPS;
    float s = 0.0f;
    for (int r = 0; r < RPS; r++) s += buf[(size_t)(r0 + r) * Hh + cc];
    atomicAdd(&out[g * Hh + cc], s * wgt * (1.0f / NPGc));
}

// ---------------- launch ----------------
extern "C" void kernel_launch(void* const* d_in, const int* in_sizes, int n_in,
                              void* d_out, int out_size) {
    const float* x       = (const float*)d_in[0];
    const int*   ei      = (const int*)d_in[1];
    const float* emb_W   = (const float*)d_in[3];
    const float* emb_b   = (const float*)d_in[4];
    const float* conv_W  = (const float*)d_in[5];
    const float* conv_b  = (const float*)d_in[6];
    const float* fconv_W = (const float*)d_in[7];
    const float* fconv_b = (const float*)d_in[8];
    const float* norm_w  = (const float*)d_in[9];
    const float* norm_b  = (const float*)d_in[10];
    const float* norm_ms = (const float*)d_in[11];
    const float* fnorm_w = (const float*)d_in[12];
    const float* fnorm_b = (const float*)d_in[13];
    const float* fnorm_ms= (const float*)d_in[14];
    const float* gate_W  = (const float*)d_in[15];
    const float* gate_b  = (const float*)d_in[16];
    float* out = (float*)d_out;

    const int* src = ei;
    const int* dst = ei + Ee;

    float *h, *ac, *bc, *af, *bf;
    __nv_bfloat16 *mb, *cb, *fb;
    uint32_t* wp;
    cudaGetSymbolAddress((void**)&h, g_h);
    cudaGetSymbolAddress((void**)&mb, g_mb);
    cudaGetSymbolAddress((void**)&cb, g_cb);
    cudaGetSymbolAddress((void**)&fb, g_fbuf);
    cudaGetSymbolAddress((void**)&wp, g_wpack);
    cudaGetSymbolAddress((void**)&ac, g_ac);
    cudaGetSymbolAddress((void**)&bc, g_bc);
    cudaGetSymbolAddress((void**)&af, g_af);
    cudaGetSymbolAddress((void**)&bf, g_bf);

    const int TPB = 256;
    const int MB = (Nn + 127) / 128;     // 391
    dim3 gemm_grid(2, MB);
    const int NBLK = (Nn + 255) / 256;   // 196
    const int WPB = (WSLOT + TPB - 1) / TPB;

    zerof_k<<<(Gg * Hh + TPB - 1) / TPB, TPB>>>(out, Gg * Hh);

    // pack weights
    wpack_k<<<WPB, TPB>>>(conv_W,              0);
    wpack_k<<<WPB, TPB>>>(conv_W + Hh * Hh,    1);
    wpack_k<<<WPB, TPB>>>(fconv_W,             2);
    wpack_k<<<WPB, TPB>>>(fconv_W + Hh * Hh,   3);
    wpack_k<<<WPB, TPB>>>(gate_W,              4);
    wpack_k<<<WPB, TPB>>>(gate_W + Hh * Hh,    5);
    embpack_k<<<(INf * Hh + TPB - 1) / TPB, TPB>>>(emb_W);

    // degrees + CSR
    cnt_zero_k<<<NBLK, TPB>>>();
    cnt_count_k<<<(Ee + TPB - 1) / TPB, TPB>>>(dst);
    dinv_k<<<NBLK, TPB>>>();
    scan1_k<<<NBLK, 256>>>();
    scan2_k<<<1, 256>>>(NBLK);
    scan3_k<<<NBLK, TPB>>>();
    fill_k<<<(Ee + TPB - 1) / TPB, TPB>>>(src, dst);

    // h = x @ emb_W + b  (tf32x3 tensor cores)
    emb_mma_k<<<gemm_grid, TPB>>>(x, emb_b, h);

    // cosine knn
    rownorm_k<<<Nn, 64>>>();
    simtopk_mma_k<<<dim3(8, Gg), TPB>>>();

    float pool_w[2] = {1.0f, 2.0f};   // gf = pool(x0) + 2*pool(x1)  (all_x[i-1] quirk)

    for (int li = 0; li < 2; li++) {
        // conv branch
        mmabf16_k<0, 0><<<gemm_grid, TPB>>>(h, wp + (size_t)li * WSLOT, mb, nullptr, nullptr);
        conv_gather_k<<<(Nn * 64) / 256, TPB>>>(conv_b + li * Hh);
        finalize_k<<<(Gg * Hh + TPB - 1) / TPB, TPB>>>(norm_w + li * Hh, norm_b + li * Hh,
                                                       norm_ms + li * Hh, ac, bc);
        // feature branch (A = norm_c(cb) fused)
        mmabf16_k<1, 1><<<gemm_grid, TPB>>>(cb, wp + (size_t)(2 + li) * WSLOT, mb, ac, bc);
        knn_agg_k<<<(Nn * 64) / 256, TPB>>>(fconv_b + li * Hh);
        finalize_k<<<(Gg * Hh + TPB - 1) / TPB, TPB>>>(fnorm_w + li * Hh, fnorm_b + li * Hh,
                                                       fnorm_ms + li * Hh, af, bf);
        // merged gate (K=512) + blend + residual -> h
        gate_k<<<gemm_grid, TPB>>>(wp + (size_t)4 * WSLOT, gate_b, h);

        pool_k<<<Gg * SPLIT, TPB>>>(h, out, pool_w[li]);
    }
    (void)in_sizes; (void)n_in; (void)out_size;
}

// round 15
// speedup vs baseline: 1.1395x; 1.0172x over previous
#include <cuda_runtime.h>
#include <cuda_bf16.h>
#include <math.h>
#include <stdint.h>

#define Nn   50000
#define Gg   100
#define NPGc 500
#define INf  128
#define Hh   256
#define Ee   800000
#define SPLIT 10
#define RPS   50
#define WSLOT (128 * 256)

// ---------------- scratch ----------------
__device__ float g_h   [Nn * Hh];
__device__ float g_xh  [Nn * Hh];
__device__ float g_xl  [Nn * Hh];
__device__ __nv_bfloat16 g_mb [Nn * Hh];
__device__ __nv_bfloat16 g_cb [Nn * Hh];
__device__ __nv_bfloat16 g_fbuf[Nn * Hh];
__device__ int   g_knn [Nn * 3];
__device__ int   g_cnt [Nn];
__device__ float g_dinv[Nn];
__device__ int   g_scan[Nn];
__device__ int   g_off [Nn];
__device__ int   g_fill[Nn];
__device__ int   g_bsum[256];
__device__ int   g_bbase[256];
__device__ int   g_esrc[Ee];
__device__ float g_ecoef[Ee];
__device__ float g_s1  [Gg * Hh];    // zero-init; finalize re-zeroes after read
__device__ float g_s2  [Gg * Hh];
__device__ float g_ac  [Gg * Hh];
__device__ float g_bc  [Gg * Hh];
__device__ float g_af  [Gg * Hh];
__device__ float g_bf  [Gg * Hh];
__device__ uint32_t g_wpack[6][WSLOT];
__device__ float g_ewh[INf * Hh];
__device__ float g_ewl[INf * Hh];

// ---- fork/join stream machinery (created once at program init; stateless use) ----
struct HxSx {
    cudaStream_t ws;
    cudaEvent_t ev_fork, ev_join;
    HxSx() {
        cudaStreamCreateWithFlags(&ws, cudaStreamNonBlocking);
        cudaEventCreateWithFlags(&ev_fork, cudaEventDisableTiming);
        cudaEventCreateWithFlags(&ev_join, cudaEventDisableTiming);
    }
};
static HxSx g_sx;

// ---------------- helpers ----------------
__device__ __forceinline__ uint32_t f2tf(float f) {
    uint32_t u;
    asm("cvt.rna.tf32.f32 %0, %1;" : "=r"(u) : "f"(f));
    return u;
}
__device__ __forceinline__ uint32_t packbf2(float lo, float hi) {
    __nv_bfloat162 p = __floats2bfloat162_rn(lo, hi);
    return *(uint32_t*)&p;
}
__device__ __forceinline__ void mma16(float* c, const uint32_t* a, const uint32_t* b) {
    asm volatile(
        "mma.sync.aligned.m16n8k16.row.col.f32.bf16.bf16.f32 "
        "{%0,%1,%2,%3}, {%4,%5,%6,%7}, {%8,%9}, {%0,%1,%2,%3};"
        : "+f"(c[0]), "+f"(c[1]), "+f"(c[2]), "+f"(c[3])
        : "r"(a[0]), "r"(a[1]), "r"(a[2]), "r"(a[3]), "r"(b[0]), "r"(b[1]));
}
__device__ __forceinline__ void mma8(float* c, const uint32_t* a, const uint32_t* b) {
    asm volatile(
        "mma.sync.aligned.m16n8k8.row.col.f32.tf32.tf32.f32 "
        "{%0,%1,%2,%3}, {%4,%5,%6,%7}, {%8,%9}, {%0,%1,%2,%3};"
        : "+f"(c[0]), "+f"(c[1]), "+f"(c[2]), "+f"(c[3])
        : "r"(a[0]), "r"(a[1]), "r"(a[2]), "r"(a[3]), "r"(b[0]), "r"(b[1]));
}
__device__ __forceinline__ float4 bf4tof4(uint2 u) {
    __nv_bfloat162 a = *(__nv_bfloat162*)&u.x;
    __nv_bfloat162 b = *(__nv_bfloat162*)&u.y;
    return make_float4(__bfloat162float(a.x), __bfloat162float(a.y),
                       __bfloat162float(b.x), __bfloat162float(b.y));
}

// ---------------- small utility kernels ----------------
__global__ void zerof_k(float* p, int n) {
    int i = blockIdx.x * blockDim.x + threadIdx.x;
    if (i < n) p[i] = 0.0f;
}
__global__ void cnt_zero_k() {
    int i = blockIdx.x * blockDim.x + threadIdx.x;
    if (i < Nn) g_cnt[i] = 0;
}
__global__ void cnt_count_k(const int* __restrict__ dst) {
    int e = blockIdx.x * blockDim.x + threadIdx.x;
    if (e < Ee) atomicAdd(&g_cnt[dst[e]], 1);
}
__global__ void dinv_k() {
    int i = blockIdx.x * blockDim.x + threadIdx.x;
    if (i < Nn) g_dinv[i] = rsqrtf((float)g_cnt[i] + 1.0f);
}
__global__ void wpack_k(const float* __restrict__ W, int slot) {
    int i = blockIdx.x * blockDim.x + threadIdx.x;
    if (i >= WSLOT) return;
    int kk = i >> 8, n = i & 255;
    __nv_bfloat162 p = __floats2bfloat162_rn(W[(2 * kk) * 256 + n], W[(2 * kk + 1) * 256 + n]);
    g_wpack[slot][i] = *(uint32_t*)&p;
}
__global__ void embpack_k(const float* __restrict__ W) {
    int i = blockIdx.x * blockDim.x + threadIdx.x;
    if (i >= INf * Hh) return;
    float w = W[i];
    float h = __uint_as_float(f2tf(w));
    g_ewh[i] = h;
    g_ewl[i] = __uint_as_float(f2tf(w - h));
}

// ---------------- CSR build ----------------
__global__ void scan1_k() {
    __shared__ int sh[256];
    int i = blockIdx.x * 256 + threadIdx.x;
    int v = (i < Nn) ? g_cnt[i] : 0;
    sh[threadIdx.x] = v;
    __syncthreads();
    for (int off = 1; off < 256; off <<= 1) {
        int t = (threadIdx.x >= off) ? sh[threadIdx.x - off] : 0;
        __syncthreads();
        sh[threadIdx.x] += t;
        __syncthreads();
    }
    if (i < Nn) g_scan[i] = sh[threadIdx.x];
    if (threadIdx.x == 255) g_bsum[blockIdx.x] = sh[255];
}
__global__ void scan2_k(int nblk) {
    __shared__ int sh[256];
    int b = threadIdx.x;
    int v = (b < nblk) ? g_bsum[b] : 0;
    sh[b] = v;
    __syncthreads();
    for (int off = 1; off < 256; off <<= 1) {
        int t = (b >= off) ? sh[b - off] : 0;
        __syncthreads();
        sh[b] += t;
        __syncthreads();
    }
    if (b < nblk) g_bbase[b] = sh[b] - v;
}
__global__ void scan3_k() {
    int i = blockIdx.x * blockDim.x + threadIdx.x;
    if (i < Nn) {
        int off = g_scan[i] - g_cnt[i] + g_bbase[i >> 8];
        g_off[i] = off;
        g_fill[i] = off;
    }
}
__global__ void fill_k(const int* __restrict__ src, const int* __restrict__ dst) {
    int e = blockIdx.x * blockDim.x + threadIdx.x;
    if (e >= Ee) return;
    int s = src[e], d = dst[e];
    int p = atomicAdd(&g_fill[d], 1);
    g_esrc[p] = s;
    g_ecoef[p] = g_dinv[s] * g_dinv[d];
}

// ---------------- emb GEMM: tf32x3 tensor cores, h = x @ emb_W + b ----------------
__global__ __launch_bounds__(256) void emb_mma_k(
    const float* __restrict__ A, const float* __restrict__ bias, float* __restrict__ out)
{
    __shared__ uint32_t AsH[128][20], AsL[128][20];
    __shared__ uint32_t BsH[16][136], BsL[16][136];

    int tid = threadIdx.x;
    int wid = tid >> 5, lane = tid & 31;
    int m0 = blockIdx.y * 128, n0 = blockIdx.x * 128;
    int wm = (wid & 3) * 32, wn = (wid >> 2) * 64;
    int group = lane >> 2, tig = lane & 3;

    float acc[2][8][4];
#pragma unroll
    for (int mt = 0; mt < 2; mt++)
#pragma unroll
        for (int nt = 0; nt < 8; nt++)
#pragma unroll
            for (int q = 0; q < 4; q++) acc[mt][nt][q] = 0.0f;

    int arow = tid >> 1, acK = (tid & 1) * 8;
    int bkr = tid >> 4, bn8 = (tid & 15) * 8;
    bool vA = (m0 + arow) < Nn;
    float4 z4 = make_float4(0.f, 0.f, 0.f, 0.f);

    for (int kt = 0; kt < 8; kt++) {
        int k0 = kt * 16;
        float4 a0 = vA ? *(const float4*)(A + (size_t)(m0 + arow) * INf + k0 + acK) : z4;
        float4 a1 = vA ? *(const float4*)(A + (size_t)(m0 + arow) * INf + k0 + acK + 4) : z4;
        float av[8] = {a0.x, a0.y, a0.z, a0.w, a1.x, a1.y, a1.z, a1.w};
#pragma unroll
        for (int j = 0; j < 8; j++) {
            uint32_t hb = f2tf(av[j]);
            AsH[arow][acK + j] = hb;
            AsL[arow][acK + j] = f2tf(av[j] - __uint_as_float(hb));
        }
        const float* bh = g_ewh + (size_t)(k0 + bkr) * 256 + n0 + bn8;
        const float* bl = g_ewl + (size_t)(k0 + bkr) * 256 + n0 + bn8;
        *(float4*)&BsH[bkr][bn8]     = *(const float4*)(bh);
        *(float4*)&BsH[bkr][bn8 + 4] = *(const float4*)(bh + 4);
        *(float4*)&BsL[bkr][bn8]     = *(const float4*)(bl);
        *(float4*)&BsL[bkr][bn8 + 4] = *(const float4*)(bl + 4);
        __syncthreads();

#pragma unroll
        for (int ks = 0; ks < 2; ks++) {
            int kb = ks * 8;
            uint32_t ah[2][4], al[2][4];
#pragma unroll
            for (int mt = 0; mt < 2; mt++) {
                int r = wm + mt * 16 + group;
                ah[mt][0] = AsH[r][kb + tig];     ah[mt][1] = AsH[r + 8][kb + tig];
                ah[mt][2] = AsH[r][kb + tig + 4]; ah[mt][3] = AsH[r + 8][kb + tig + 4];
                al[mt][0] = AsL[r][kb + tig];     al[mt][1] = AsL[r + 8][kb + tig];
                al[mt][2] = AsL[r][kb + tig + 4]; al[mt][3] = AsL[r + 8][kb + tig + 4];
            }
            uint32_t bh2[8][2], bl2[8][2];
#pragma unroll
            for (int nt = 0; nt < 8; nt++) {
                int cc = wn + nt * 8 + group;
                bh2[nt][0] = BsH[kb + tig][cc]; bh2[nt][1] = BsH[kb + tig + 4][cc];
                bl2[nt][0] = BsL[kb + tig][cc]; bl2[nt][1] = BsL[kb + tig + 4][cc];
            }
#pragma unroll
            for (int mt = 0; mt < 2; mt++)
#pragma unroll
                for (int nt = 0; nt < 8; nt++) {
                    mma8(acc[mt][nt], ah[mt], bh2[nt]);
                    mma8(acc[mt][nt], ah[mt], bl2[nt]);
                    mma8(acc[mt][nt], al[mt], bh2[nt]);
                }
        }
        __syncthreads();
    }

#pragma unroll
    for (int mt = 0; mt < 2; mt++)
#pragma unroll
        for (int half = 0; half < 2; half++) {
            int row = m0 + wm + mt * 16 + group + half * 8;
            if (row >= Nn) continue;
#pragma unroll
            for (int nt = 0; nt < 8; nt++) {
                int col = n0 + wn + nt * 8 + 2 * tig;
                size_t base = (size_t)row * 256 + col;
                out[base]     = acc[mt][nt][half * 2 + 0] + bias[col];
                out[base + 1] = acc[mt][nt][half * 2 + 1] + bias[col + 1];
            }
        }
}

// ---------------- bf16 mma GEMM -> mb (bf16). NORMA: fused graphnorm+leaky on A ----------------
template <int NORMA, int ABF>
__global__ __launch_bounds__(256) void mmabf16_k(
    const void* __restrict__ Araw, const uint32_t* __restrict__ Bp,
    __nv_bfloat16* __restrict__ bout,
    const float* __restrict__ nAa, const float* __restrict__ nAb)
{
    __shared__ uint32_t As[128][20];
    __shared__ uint32_t Bs[16][136];

    int tid = threadIdx.x;
    int wid = tid >> 5, lane = tid & 31;
    int m0 = blockIdx.y * 128, n0 = blockIdx.x * 128;
    int wm = (wid & 3) * 32, wn = (wid >> 2) * 64;
    int group = lane >> 2, tig = lane & 3;

    float acc[2][8][4];
#pragma unroll
    for (int mt = 0; mt < 2; mt++)
#pragma unroll
        for (int nt = 0; nt < 8; nt++)
#pragma unroll
            for (int q = 0; q < 4; q++) acc[mt][nt][q] = 0.0f;

    int arow = tid >> 3, acK = (tid & 7) * 4;
    int bkr = tid >> 4, bn8 = (tid & 15) * 8;

    bool vAi[4];
    int ggA[4];
#pragma unroll
    for (int i = 0; i < 4; i++) {
        int r = m0 + arow + 32 * i;
        vAi[i] = r < Nn;
        ggA[i] = vAi[i] ? (r / NPGc) : 0;
    }

    const float* Af = (const float*)Araw;
    const __nv_bfloat16* Ab = (const __nv_bfloat16*)Araw;
    float4 paf[4];
    uint2 pab[4];
    uint4 pb[2];
    float4 z4 = make_float4(0.f, 0.f, 0.f, 0.f);
    uint2 z2 = make_uint2(0, 0);

#pragma unroll
    for (int i = 0; i < 4; i++) {
        int r = m0 + arow + 32 * i;
        if (ABF) pab[i] = vAi[i] ? *(const uint2*)(Ab + (size_t)r * 256 + acK) : z2;
        else     paf[i] = vAi[i] ? *(const float4*)(Af + (size_t)r * 256 + acK) : z4;
    }
#pragma unroll
    for (int j = 0; j < 2; j++)
        pb[j] = *(const uint4*)(Bp + (size_t)bkr * 256 + n0 + bn8 + 4 * j);

    for (int kt = 0; kt < 8; kt++) {
#pragma unroll
        for (int i = 0; i < 4; i++) {
            float4 w = ABF ? bf4tof4(pab[i]) : paf[i];
            if (NORMA) {
                if (vAi[i]) {
                    float4 a4 = *(const float4*)(nAa + ggA[i] * 256 + kt * 32 + acK);
                    float4 b4 = *(const float4*)(nAb + ggA[i] * 256 + kt * 32 + acK);
                    w.x = fmaf(w.x, a4.x, b4.x); w.x = w.x > 0.f ? w.x : 0.01f * w.x;
                    w.y = fmaf(w.y, a4.y, b4.y); w.y = w.y > 0.f ? w.y : 0.01f * w.y;
                    w.z = fmaf(w.z, a4.z, b4.z); w.z = w.z > 0.f ? w.z : 0.01f * w.z;
                    w.w = fmaf(w.w, a4.w, b4.w); w.w = w.w > 0.f ? w.w : 0.01f * w.w;
                }
            }
            As[arow + 32 * i][(acK >> 1) + 0] = packbf2(w.x, w.y);
            As[arow + 32 * i][(acK >> 1) + 1] = packbf2(w.z, w.w);
        }
#pragma unroll
        for (int j = 0; j < 2; j++)
            *(uint4*)&Bs[bkr][bn8 + 4 * j] = pb[j];
        __syncthreads();

        if (kt < 7) {
            int k0 = (kt + 1) * 32;
#pragma unroll
            for (int i = 0; i < 4; i++) {
                int r = m0 + arow + 32 * i;
                if (ABF) pab[i] = vAi[i] ? *(const uint2*)(Ab + (size_t)r * 256 + k0 + acK) : z2;
                else     paf[i] = vAi[i] ? *(const float4*)(Af + (size_t)r * 256 + k0 + acK) : z4;
            }
#pragma unroll
            for (int j = 0; j < 2; j++)
                pb[j] = *(const uint4*)(Bp + (size_t)((k0 >> 1) + bkr) * 256 + n0 + bn8 + 4 * j);
        }

#pragma unroll
        for (int s = 0; s < 2; s++) {
            uint32_t afr[2][4];
#pragma unroll
            for (int mt = 0; mt < 2; mt++) {
                int r = wm + mt * 16 + group;
                afr[mt][0] = As[r][s * 8 + tig];
                afr[mt][1] = As[r + 8][s * 8 + tig];
                afr[mt][2] = As[r][s * 8 + tig + 4];
                afr[mt][3] = As[r + 8][s * 8 + tig + 4];
            }
            uint32_t bfr[8][2];
#pragma unroll
            for (int nt = 0; nt < 8; nt++) {
                int cc = wn + nt * 8 + group;
                bfr[nt][0] = Bs[s * 8 + tig][cc];
                bfr[nt][1] = Bs[s * 8 + tig + 4][cc];
            }
#pragma unroll
            for (int mt = 0; mt < 2; mt++)
#pragma unroll
                for (int nt = 0; nt < 8; nt++) mma16(acc[mt][nt], afr[mt], bfr[nt]);
        }
        __syncthreads();
    }

#pragma unroll
    for (int mt = 0; mt < 2; mt++)
#pragma unroll
        for (int half = 0; half < 2; half++) {
            int row = m0 + wm + mt * 16 + group + half * 8;
            if (row >= Nn) continue;
#pragma unroll
            for (int nt = 0; nt < 8; nt++) {
                int col = n0 + wn + nt * 8 + 2 * tig;
                size_t base = (size_t)row * 256 + col;
                __nv_bfloat162 p = __floats2bfloat162_rn(acc[mt][nt][half * 2 + 0],
                                                         acc[mt][nt][half * 2 + 1]);
                *(__nv_bfloat162*)(bout + base) = p;
            }
        }
}

// ---------------- merged gate GEMM: K=512 + blend + residual ----------------
__global__ __launch_bounds__(256) void gate_k(
    const uint32_t* __restrict__ Bp, const float* __restrict__ gate_b,
    float* __restrict__ h)
{
    __shared__ uint32_t As[128][20];
    __shared__ uint32_t Bs[16][136];

    int tid = threadIdx.x;
    int wid = tid >> 5, lane = tid & 31;
    int m0 = blockIdx.y * 128, n0 = blockIdx.x * 128;
    int wm = (wid & 3) * 32, wn = (wid >> 2) * 64;
    int group = lane >> 2, tig = lane & 3;

    float acc[2][8][4];
#pragma unroll
    for (int mt = 0; mt < 2; mt++)
#pragma unroll
        for (int nt = 0; nt < 8; nt++)
#pragma unroll
            for (int q = 0; q < 4; q++) acc[mt][nt][q] = 0.0f;

    int arow = tid >> 3, acK = (tid & 7) * 4;
    int bkr = tid >> 4, bn8 = (tid & 15) * 8;

    bool vAi[4];
    int ggA[4];
#pragma unroll
    for (int i = 0; i < 4; i++) {
        int r = m0 + arow + 32 * i;
        vAi[i] = r < Nn;
        ggA[i] = vAi[i] ? (r / NPGc) : 0;
    }

    uint2 pab[4];
    uint4 pb[2];
    uint2 z2 = make_uint2(0, 0);

#pragma unroll
    for (int i = 0; i < 4; i++) {
        int r = m0 + arow + 32 * i;
        pab[i] = vAi[i] ? *(const uint2*)(g_cb + (size_t)r * 256 + acK) : z2;
    }
#pragma unroll
    for (int j = 0; j < 2; j++)
        pb[j] = *(const uint4*)(Bp + (size_t)bkr * 256 + n0 + bn8 + 4 * j);

    for (int kt = 0; kt < 16; kt++) {
        int khalf = kt >> 3;                 // 0: c-branch, 1: f-branch
        int koff = (kt & 7) * 32;
        const float* na = khalf ? g_af : g_ac;
        const float* nb = khalf ? g_bf : g_bc;
#pragma unroll
        for (int i = 0; i < 4; i++) {
            float4 w = bf4tof4(pab[i]);
            if (vAi[i]) {
                float4 a4 = *(const float4*)(na + ggA[i] * 256 + koff + acK);
                float4 b4 = *(const float4*)(nb + ggA[i] * 256 + koff + acK);
                w.x = fmaf(w.x, a4.x, b4.x); w.x = w.x > 0.f ? w.x : 0.01f * w.x;
                w.y = fmaf(w.y, a4.y, b4.y); w.y = w.y > 0.f ? w.y : 0.01f * w.y;
                w.z = fmaf(w.z, a4.z, b4.z); w.z = w.z > 0.f ? w.z : 0.01f * w.z;
                w.w = fmaf(w.w, a4.w, b4.w); w.w = w.w > 0.f ? w.w : 0.01f * w.w;
            }
            As[arow + 32 * i][(acK >> 1) + 0] = packbf2(w.x, w.y);
            As[arow + 32 * i][(acK >> 1) + 1] = packbf2(w.z, w.w);
        }
#pragma unroll
        for (int j = 0; j < 2; j++)
            *(uint4*)&Bs[bkr][bn8 + 4 * j] = pb[j];
        __syncthreads();

        if (kt < 15) {
            int nk = kt + 1;
            const __nv_bfloat16* Asrc = (nk < 8) ? g_cb : g_fbuf;
            int nkoff = (nk & 7) * 32;
#pragma unroll
            for (int i = 0; i < 4; i++) {
                int r = m0 + arow + 32 * i;
                pab[i] = vAi[i] ? *(const uint2*)(Asrc + (size_t)r * 256 + nkoff + acK) : z2;
            }
#pragma unroll
            for (int j = 0; j < 2; j++)
                pb[j] = *(const uint4*)(Bp + (size_t)((nk * 16) + bkr) * 256 + n0 + bn8 + 4 * j);
        }

#pragma unroll
        for (int s = 0; s < 2; s++) {
            uint32_t afr[2][4];
#pragma unroll
            for (int mt = 0; mt < 2; mt++) {
                int r = wm + mt * 16 + group;
                afr[mt][0] = As[r][s * 8 + tig];
                afr[mt][1] = As[r + 8][s * 8 + tig];
                afr[mt][2] = As[r][s * 8 + tig + 4];
                afr[mt][3] = As[r + 8][s * 8 + tig + 4];
            }
            uint32_t bfr[8][2];
#pragma unroll
            for (int nt = 0; nt < 8; nt++) {
                int cc = wn + nt * 8 + group;
                bfr[nt][0] = Bs[s * 8 + tig][cc];
                bfr[nt][1] = Bs[s * 8 + tig + 4][cc];
            }
#pragma unroll
            for (int mt = 0; mt < 2; mt++)
#pragma unroll
                for (int nt = 0; nt < 8; nt++) mma16(acc[mt][nt], afr[mt], bfr[nt]);
        }
        __syncthreads();
    }

    // epilogue: g = sigmoid(acc + gate_b); h = g*leaky(norm_c(c)) + (1-g)*leaky(norm_f(f)) + h
#pragma unroll
    for (int mt = 0; mt < 2; mt++)
#pragma unroll
        for (int half = 0; half < 2; half++) {
            int row = m0 + wm + mt * 16 + group + half * 8;
            if (row >= Nn) continue;
            int gg = row / NPGc;
#pragma unroll
            for (int nt = 0; nt < 8; nt++) {
                int col = n0 + wn + nt * 8 + 2 * tig;
                size_t base = (size_t)row * 256 + col;
                int cb2 = gg * 256 + col;
                float s0 = acc[mt][nt][half * 2 + 0] + gate_b[col];
                float s1 = acc[mt][nt][half * 2 + 1] + gate_b[col + 1];
                float gt0 = 1.0f / (1.0f + expf(-s0));
                float gt1 = 1.0f / (1.0f + expf(-s1));
                __nv_bfloat162 cv = *(const __nv_bfloat162*)(g_cb + base);
                __nv_bfloat162 fv = *(const __nv_bfloat162*)(g_fbuf + base);
                float c0 = fmaf(__bfloat162float(cv.x), g_ac[cb2],     g_bc[cb2]);
                float c1 = fmaf(__bfloat162float(cv.y), g_ac[cb2 + 1], g_bc[cb2 + 1]);
                c0 = c0 > 0.f ? c0 : 0.01f * c0;
                c1 = c1 > 0.f ? c1 : 0.01f * c1;
                float f0 = fmaf(__bfloat162float(fv.x), g_af[cb2],     g_bf[cb2]);
                float f1 = fmaf(__bfloat162float(fv.y), g_af[cb2 + 1], g_bf[cb2 + 1]);
                f0 = f0 > 0.f ? f0 : 0.01f * f0;
                f1 = f1 > 0.f ? f1 : 0.01f * f1;
                h[base]     = gt0 * c0 + (1.0f - gt0) * f0 + h[base];
                h[base + 1] = gt1 * c1 + (1.0f - gt1) * f1 + h[base + 1];
            }
        }
}

// ---------------- row normalize + tf32 hi/lo split ----------------
__global__ void rownorm_k() {
    int row = blockIdx.x;
    int t = threadIdx.x;
    float4 v = *(const float4*)(g_h + (size_t)row * Hh + t * 4);
    float s = v.x * v.x + v.y * v.y + v.z * v.z + v.w * v.w;
    __shared__ float sh[64];
    sh[t] = s;
    __syncthreads();
    for (int off = 32; off > 0; off >>= 1) {
        if (t < off) sh[t] += sh[t + off];
        __syncthreads();
    }
    float inv = 1.0f / (sqrtf(sh[0]) + 1e-12f);
    float n0 = v.x * inv, n1 = v.y * inv, n2 = v.z * inv, n3 = v.w * inv;
    float h0 = __uint_as_float(f2tf(n0));
    float h1 = __uint_as_float(f2tf(n1));
    float h2 = __uint_as_float(f2tf(n2));
    float h3 = __uint_as_float(f2tf(n3));
    *(float4*)(g_xh + (size_t)row * Hh + t * 4) = make_float4(h0, h1, h2, h3);
    *(float4*)(g_xl + (size_t)row * Hh + t * 4) =
        make_float4(__uint_as_float(f2tf(n0 - h0)), __uint_as_float(f2tf(n1 - h1)),
                    __uint_as_float(f2tf(n2 - h2)), __uint_as_float(f2tf(n3 - h3)));
}

// ---------------- top-3 insert ----------------
__device__ __forceinline__ void tk3(float v, int id, float* tv, int* ti) {
    if (v > tv[0] || (v == tv[0] && id < ti[0])) {
        tv[2] = tv[1]; ti[2] = ti[1];
        tv[1] = tv[0]; ti[1] = ti[0];
        tv[0] = v;     ti[0] = id;
    } else if (v > tv[1] || (v == tv[1] && id < ti[1])) {
        tv[2] = tv[1]; ti[2] = ti[1];
        tv[1] = v;     ti[1] = id;
    } else if (v > tv[2] || (v == tv[2] && id < ti[2])) {
        tv[2] = v;     ti[2] = id;
    }
}

// ---------------- fused 3xTF32 sim + top-3 ----------------
__global__ __launch_bounds__(256) void simtopk_mma_k() {
    int g = blockIdx.y;
    int i0 = blockIdx.x * 64;
    const float* XH = g_xh + (size_t)g * NPGc * Hh;
    const float* XL = g_xl + (size_t)g * NPGc * Hh;
    int goff = g * NPGc;

    __shared__ uint32_t Ah[64][20], Al[64][20], Bh[128][20], Bl[128][20];
    __shared__ float redv[4][64][3];
    __shared__ int   redi[4][64][3];

    int tid = threadIdx.x;
    int wid = tid >> 5, lane = tid & 31;
    int group = lane >> 2, tig = lane & 3;
    int wrow = (wid & 1) * 32, wcol = (wid >> 1) * 32;

    float tv[4][3];
    int ti[4][3];
#pragma unroll
    for (int r = 0; r < 4; r++)
#pragma unroll
        for (int c = 0; c < 3; c++) { tv[r][c] = -1e30f; ti[r][c] = 0x7fffffff; }

    int rA = tid >> 2, qA = (tid & 3) * 4;
    int rB = tid >> 1, qB = (tid & 1) * 8;
    bool vA = (i0 + rA) < NPGc;
    const float* ahp = XH + (size_t)(i0 + rA) * Hh + qA;
    const float* alp = XL + (size_t)(i0 + rA) * Hh + qA;
    float4 zh = make_float4(0.f, 0.f, 0.f, 0.f);

    for (int jt = 0; jt < 4; jt++) {
        int j0 = jt * 128;
        bool vB = (j0 + rB) < NPGc;
        const float* bhp = XH + (size_t)(j0 + rB) * Hh + qB;
        const float* blp = XL + (size_t)(j0 + rB) * Hh + qB;

        float acc[2][4][4];
#pragma unroll
        for (int mt = 0; mt < 2; mt++)
#pragma unroll
            for (int nt = 0; nt < 4; nt++)
#pragma unroll
                for (int q = 0; q < 4; q++) acc[mt][nt][q] = 0.0f;

        for (int kt = 0; kt < 16; kt++) {
            int k0 = kt * 16;
            float4 va_h = vA ? *(const float4*)(ahp + k0) : zh;
            float4 va_l = vA ? *(const float4*)(alp + k0) : zh;
            *(uint4*)&Ah[rA][qA] = *(uint4*)&va_h;
            *(uint4*)&Al[rA][qA] = *(uint4*)&va_l;
            float4 vb_h0 = vB ? *(const float4*)(bhp + k0) : zh;
            float4 vb_h1 = vB ? *(const float4*)(bhp + k0 + 4) : zh;
            float4 vb_l0 = vB ? *(const float4*)(blp + k0) : zh;
            float4 vb_l1 = vB ? *(const float4*)(blp + k0 + 4) : zh;
            *(uint4*)&Bh[rB][qB]     = *(uint4*)&vb_h0;
            *(uint4*)&Bh[rB][qB + 4] = *(uint4*)&vb_h1;
            *(uint4*)&Bl[rB][qB]     = *(uint4*)&vb_l0;
            *(uint4*)&Bl[rB][qB + 4] = *(uint4*)&vb_l1;
            __syncthreads();

#pragma unroll
            for (int ks = 0; ks < 2; ks++) {
                int kb = ks * 8;
                uint32_t ah[2][4], al[2][4];
#pragma unroll
                for (int mt = 0; mt < 2; mt++) {
                    int r = wrow + mt * 16 + group;
                    ah[mt][0] = Ah[r][kb + tig];     ah[mt][1] = Ah[r + 8][kb + tig];
                    ah[mt][2] = Ah[r][kb + tig + 4]; ah[mt][3] = Ah[r + 8][kb + tig + 4];
                    al[mt][0] = Al[r][kb + tig];     al[mt][1] = Al[r + 8][kb + tig];
                    al[mt][2] = Al[r][kb + tig + 4]; al[mt][3] = Al[r + 8][kb + tig + 4];
                }
                uint32_t bh[4][2], bl[4][2];
#pragma unroll
                for (int nt = 0; nt < 4; nt++) {
                    int cc = wcol + nt * 8 + group;
                    bh[nt][0] = Bh[cc][kb + tig]; bh[nt][1] = Bh[cc][kb + tig + 4];
                    bl[nt][0] = Bl[cc][kb + tig]; bl[nt][1] = Bl[cc][kb + tig + 4];
                }
#pragma unroll
                for (int mt = 0; mt < 2; mt++)
#pragma unroll
                    for (int nt = 0; nt < 4; nt++) {
                        mma8(acc[mt][nt], ah[mt], bh[nt]);
                        mma8(acc[mt][nt], ah[mt], bl[nt]);
                        mma8(acc[mt][nt], al[mt], bh[nt]);
                    }
            }
            __syncthreads();
        }

#pragma unroll
        for (int mt = 0; mt < 2; mt++)
#pragma unroll
            for (int nt = 0; nt < 4; nt++)
#pragma unroll
                for (int q = 0; q < 4; q++) {
                    int half = q >> 1, cbit = q & 1;
                    int col = j0 + wcol + nt * 8 + 2 * tig + cbit;
                    if (col < NPGc) {
                        int r = mt * 2 + half;
                        tk3(acc[mt][nt][q], goff + col, tv[r], ti[r]);
                    }
                }
    }

#pragma unroll
    for (int x = 1; x <= 2; x <<= 1) {
#pragma unroll
        for (int r = 0; r < 4; r++) {
            float ov[3]; int oi[3];
#pragma unroll
            for (int c = 0; c < 3; c++) {
                ov[c] = __shfl_xor_sync(0xffffffff, tv[r][c], x);
                oi[c] = __shfl_xor_sync(0xffffffff, ti[r][c], x);
            }
#pragma unroll
            for (int c = 0; c < 3; c++) tk3(ov[c], oi[c], tv[r], ti[r]);
        }
    }

    if (tig == 0) {
        int w4 = wid >> 1;
#pragma unroll
        for (int r = 0; r < 4; r++) {
            int mt = r >> 1, half = r & 1;
            int rowl = wrow + mt * 16 + half * 8 + group;
#pragma unroll
            for (int c = 0; c < 3; c++) {
                redv[w4][rowl][c] = tv[r][c];
                redi[w4][rowl][c] = ti[r][c];
            }
        }
    }
    __syncthreads();

    if (tid < 64) {
        int rowg = i0 + tid;
        if (rowg < NPGc) {
            float fv[3]; int fi[3];
#pragma unroll
            for (int c = 0; c < 3; c++) { fv[c] = redv[0][tid][c]; fi[c] = redi[0][tid][c]; }
#pragma unroll
            for (int w = 1; w < 4; w++)
#pragma unroll
                for (int c = 0; c < 3; c++) tk3(redv[w][tid][c], redi[w][tid][c], fv, fi);
            int* o = g_knn + (size_t)(goff + rowg) * 3;
            o[0] = fi[0]; o[1] = fi[1]; o[2] = fi[2];
        }
    }
}

// ---------------- gathers with fused stats + bf16 output ----------------
__device__ __forceinline__ void gather_epi(float4 acc, int tid, int blk,
                                           __nv_bfloat16* obuf, size_t obase) {
    __shared__ float sh1[1024], sh2[1024];
    uint2 p;
    p.x = packbf2(acc.x, acc.y);
    p.y = packbf2(acc.z, acc.w);
    *(uint2*)(obuf + obase) = p;
    *(float4*)&sh1[tid * 4] = acc;
    *(float4*)&sh2[tid * 4] = make_float4(acc.x * acc.x, acc.y * acc.y,
                                          acc.z * acc.z, acc.w * acc.w);
    __syncthreads();
    if (tid < 64) {
        float4 s1 = make_float4(0.f, 0.f, 0.f, 0.f);
        float4 s2 = make_float4(0.f, 0.f, 0.f, 0.f);
#pragma unroll
        for (int nd = 0; nd < 4; nd++) {
            float4 a = *(float4*)&sh1[(nd * 64 + tid) * 4];
            float4 b = *(float4*)&sh2[(nd * 64 + tid) * 4];
            s1.x += a.x; s1.y += a.y; s1.z += a.z; s1.w += a.w;
            s2.x += b.x; s2.y += b.y; s2.z += b.z; s2.w += b.w;
        }
        int g = (blk * 4) / NPGc;
        int base = g * 256 + tid * 4;
        atomicAdd(&g_s1[base + 0], s1.x); atomicAdd(&g_s1[base + 1], s1.y);
        atomicAdd(&g_s1[base + 2], s1.z); atomicAdd(&g_s1[base + 3], s1.w);
        atomicAdd(&g_s2[base + 0], s2.x); atomicAdd(&g_s2[base + 1], s2.y);
        atomicAdd(&g_s2[base + 2], s2.z); atomicAdd(&g_s2[base + 3], s2.w);
    }
}

__global__ __launch_bounds__(256) void conv_gather_k(const float* __restrict__ bias) {
    int tid = threadIdx.x;
    int t = blockIdx.x * 256 + tid;
    int n = t >> 6, q = t & 63;
    float d0 = g_dinv[n];
    float co = d0 * d0;
    float4 a = bf4tof4(*(const uint2*)(g_mb + (size_t)n * 256 + q * 4));
    float4 bv = ((const float4*)bias)[q];
    float4 acc = make_float4(a.x * co + bv.x, a.y * co + bv.y,
                             a.z * co + bv.z, a.w * co + bv.w);
    int off = g_off[n], cnt = g_cnt[n];
    for (int j = 0; j < cnt; j++) {
        int s = g_esrc[off + j];
        float cf = g_ecoef[off + j];
        float4 v = bf4tof4(*(const uint2*)(g_mb + (size_t)s * 256 + q * 4));
        acc.x += v.x * cf; acc.y += v.y * cf; acc.z += v.z * cf; acc.w += v.w * cf;
    }
    gather_epi(acc, tid, blockIdx.x, g_cb, (size_t)n * 256 + q * 4);
}

__global__ __launch_bounds__(256) void knn_agg_k(const float* __restrict__ bias) {
    int tid = threadIdx.x;
    int t = blockIdx.x * 256 + tid;
    int n = t >> 6, q = t & 63;
    int i0 = g_knn[n * 3 + 0], i1 = g_knn[n * 3 + 1], i2 = g_knn[n * 3 + 2];
    float4 a = bf4tof4(*(const uint2*)(g_mb + (size_t)n * 256 + q * 4));
    float4 b = bf4tof4(*(const uint2*)(g_mb + (size_t)i0 * 256 + q * 4));
    float4 c = bf4tof4(*(const uint2*)(g_mb + (size_t)i1 * 256 + q * 4));
    float4 d = bf4tof4(*(const uint2*)(g_mb + (size_t)i2 * 256 + q * 4));
    float4 bv = ((const float4*)bias)[q];
    float4 acc = make_float4(0.25f * (a.x + b.x + c.x + d.x) + bv.x,
                             0.25f * (a.y + b.y + c.y + d.y) + bv.y,
                             0.25f * (a.z + b.z + c.z + d.z) + bv.z,
                             0.25f * (a.w + b.w + c.w + d.w) + bv.w);
    gather_epi(acc, tid, blockIdx.x, g_fbuf, (size_t)n * 256 + q * 4);
}

// ---------------- finalize norm params (self-zeroing stats) ----------------
__global__ void finalize_k(const float* __restrict__ w, const float* __restrict__ b,
                           const float* __restrict__ ms,
                           float* __restrict__ alpha, float* __restrict__ beta) {
    int i = blockIdx.x * blockDim.x + threadIdx.x;
    if (i >= Gg * Hh) return;
    int cc = i & 255;
    float mean = g_s1[i] * (1.0f / NPGc);
    float ex2 = g_s2[i] * (1.0f / NPGc);
    float m = ms[cc];
    float var = ex2 - mean * mean * m * (2.0f - m);
    float a = w[cc] * rsqrtf(var + 1e-5f);
    alpha[i] = a;
    beta[i] = b[cc] - a * m * mean;
    g_s1[i] = 0.0f;
    g_s2[i] = 0.0f;
}

// ---------------- pooling ----------------
__global__ void pool_k(const float* __restrict__ buf, float* __restrict__ out, float wgt) {
    int b = blockIdx.x;
    int g = b / SPLIT, sp = b % SPLIT;
    int cc = threadIdx.x;
    int r0 = g * NPGc + sp * RPS;
    float s = 0.0f;
    for (int r = 0; r < RPS; r++) s += buf[(size_t)(r0 + r) * Hh + cc];
    atomicAdd(&out[g * Hh + cc], s * wgt * (1.0f / NPGc));
}

// ---------------- launch ----------------
extern "C" void kernel_launch(void* const* d_in, const int* in_sizes, int n_in,
                              void* d_out, int out_size) {
    const float* x       = (const float*)d_in[0];
    const int*   ei      = (const int*)d_in[1];
    const float* emb_W   = (const float*)d_in[3];
    const float* emb_b   = (const float*)d_in[4];
    const float* conv_W  = (const float*)d_in[5];
    const float* conv_b  = (const float*)d_in[6];
    const float* fconv_W = (const float*)d_in[7];
    const float* fconv_b = (const float*)d_in[8];
    const float* norm_w  = (const float*)d_in[9];
    const float* norm_b  = (const float*)d_in[10];
    const float* norm_ms = (const float*)d_in[11];
    const float* fnorm_w = (const float*)d_in[12];
    const float* fnorm_b = (const float*)d_in[13];
    const float* fnorm_ms= (const float*)d_in[14];
    const float* gate_W  = (const float*)d_in[15];
    const float* gate_b  = (const float*)d_in[16];
    float* out = (float*)d_out;

    const int* src = ei;
    const int* dst = ei + Ee;

    float *h, *ac, *bc, *af, *bf;
    __nv_bfloat16 *mb, *cb, *fb;
    uint32_t* wp;
    cudaGetSymbolAddress((void**)&h, g_h);
    cudaGetSymbolAddress((void**)&mb, g_mb);
    cudaGetSymbolAddress((void**)&cb, g_cb);
    cudaGetSymbolAddress((void**)&fb, g_fbuf);
    cudaGetSymbolAddress((void**)&wp, g_wpack);
    cudaGetSymbolAddress((void**)&ac, g_ac);
    cudaGetSymbolAddress((void**)&bc, g_bc);
    cudaGetSymbolAddress((void**)&af, g_af);
    cudaGetSymbolAddress((void**)&bf, g_bf);

    const int TPB = 256;
    const int MB = (Nn + 127) / 128;     // 391
    dim3 gemm_grid(2, MB);
    const int NBLK = (Nn + 255) / 256;   // 196
    const int WPB = (WSLOT + TPB - 1) / TPB;
    cudaStream_t ws = g_sx.ws;

    // ---- fork: worker stream handles weight packing + CSR build ----
    cudaEventRecord(g_sx.ev_fork, 0);
    cudaStreamWaitEvent(ws, g_sx.ev_fork, 0);

    // worker chain (independent of main chain buffers)
    wpack_k<<<WPB, TPB, 0, ws>>>(conv_W,              0);
    wpack_k<<<WPB, TPB, 0, ws>>>(conv_W + Hh * Hh,    1);
    wpack_k<<<WPB, TPB, 0, ws>>>(fconv_W,             2);
    wpack_k<<<WPB, TPB, 0, ws>>>(fconv_W + Hh * Hh,   3);
    wpack_k<<<WPB, TPB, 0, ws>>>(gate_W,              4);
    wpack_k<<<WPB, TPB, 0, ws>>>(gate_W + Hh * Hh,    5);
    cnt_zero_k<<<NBLK, TPB, 0, ws>>>();
    cnt_count_k<<<(Ee + TPB - 1) / TPB, TPB, 0, ws>>>(dst);
    dinv_k<<<NBLK, TPB, 0, ws>>>();
    scan1_k<<<NBLK, 256, 0, ws>>>();
    scan2_k<<<1, 256, 0, ws>>>(NBLK);
    scan3_k<<<NBLK, TPB, 0, ws>>>();
    fill_k<<<(Ee + TPB - 1) / TPB, TPB, 0, ws>>>(src, dst);
    cudaEventRecord(g_sx.ev_join, ws);

    // main chain: emb GEMM + cosine knn
    zerof_k<<<(Gg * Hh + TPB - 1) / TPB, TPB>>>(out, Gg * Hh);
    embpack_k<<<(INf * Hh + TPB - 1) / TPB, TPB>>>(emb_W);
    emb_mma_k<<<gemm_grid, TPB>>>(x, emb_b, h);
    rownorm_k<<<Nn, 64>>>();
    simtopk_mma_k<<<dim3(8, Gg), TPB>>>();

    // ---- join: layer loop needs both chains ----
    cudaStreamWaitEvent(0, g_sx.ev_join, 0);

    float pool_w[2] = {1.0f, 2.0f};   // gf = pool(x0) + 2*pool(x1)  (all_x[i-1] quirk)

    for (int li = 0; li < 2; li++) {
        // conv branch
        mmabf16_k<0, 0><<<gemm_grid, TPB>>>(h, wp + (size_t)li * WSLOT, mb, nullptr, nullptr);
        conv_gather_k<<<(Nn * 64) / 256, TPB>>>(conv_b + li * Hh);
        finalize_k<<<(Gg * Hh + TPB - 1) / TPB, TPB>>>(norm_w + li * Hh, norm_b + li * Hh,
                                                       norm_ms + li * Hh, ac, bc);
        // feature branch (A = norm_c(cb) fused)
        mmabf16_k<1, 1><<<gemm_grid, TPB>>>(cb, wp + (size_t)(2 + li) * WSLOT, mb, ac, bc);
        knn_agg_k<<<(Nn * 64) / 256, TPB>>>(fconv_b + li * Hh);
        finalize_k<<<(Gg * Hh + TPB - 1) / TPB, TPB>>>(fnorm_w + li * Hh, fnorm_b + li * Hh,
                                                       fnorm_ms + li * Hh, af, bf);
        // merged gate (K=512) + blend + residual -> h
        gate_k<<<gemm_grid, TPB>>>(wp + (size_t)4 * WSLOT, gate_b, h);

        pool_k<<<Gg * SPLIT, TPB>>>(h, out, pool_w[li]);
    }
    (void)in_sizes; (void)n_in; (void)out_size;
}

// round 16
// speedup vs baseline: 1.1952x; 1.0488x over previous
#include <cuda_runtime.h>
#include <cuda_bf16.h>
#include <math.h>
#include <stdint.h>

#define Nn   50000
#define Gg   100
#define NPGc 500
#define INf  128
#define Hh   256
#define Ee   800000
#define SPLIT 10
#define RPS   50
#define WSLOT (128 * 256)

// ---------------- scratch ----------------
__device__ float g_h   [Nn * Hh];
__device__ float g_xh  [Nn * Hh];
__device__ float g_xl  [Nn * Hh];
__device__ __nv_bfloat16 g_mb [Nn * Hh];
__device__ __nv_bfloat16 g_cb [Nn * Hh];
__device__ __nv_bfloat16 g_fbuf[Nn * Hh];
__device__ int   g_knn [Nn * 3];
__device__ int   g_cnt [Nn];
__device__ float g_dinv[Nn];
__device__ int   g_scan[Nn];
__device__ int   g_off [Nn];
__device__ int   g_fill[Nn];
__device__ int   g_bsum[256];
__device__ int   g_bbase[256];
__device__ int   g_esrc[Ee];
__device__ float g_ecoef[Ee];
__device__ float g_s1  [Gg * Hh];    // zero-init; finalize re-zeroes after read
__device__ float g_s2  [Gg * Hh];
__device__ float g_ac  [Gg * Hh];
__device__ float g_bc  [Gg * Hh];
__device__ float g_af  [Gg * Hh];
__device__ float g_bf  [Gg * Hh];
__device__ uint32_t g_wpack[6][WSLOT];
__device__ float g_ewh[INf * Hh];
__device__ float g_ewl[INf * Hh];

// ---- fork/join stream machinery (created once at program init; stateless use) ----
struct HxSx {
    cudaStream_t ws;
    cudaEvent_t ev_fork, ev_h, ev_join;
    HxSx() {
        cudaStreamCreateWithFlags(&ws, cudaStreamNonBlocking);
        cudaEventCreateWithFlags(&ev_fork, cudaEventDisableTiming);
        cudaEventCreateWithFlags(&ev_h, cudaEventDisableTiming);
        cudaEventCreateWithFlags(&ev_join, cudaEventDisableTiming);
    }
};
static HxSx g_sx;

// ---------------- helpers ----------------
__device__ __forceinline__ uint32_t f2tf(float f) {
    uint32_t u;
    asm("cvt.rna.tf32.f32 %0, %1;" : "=r"(u) : "f"(f));
    return u;
}
__device__ __forceinline__ uint32_t packbf2(float lo, float hi) {
    __nv_bfloat162 p = __floats2bfloat162_rn(lo, hi);
    return *(uint32_t*)&p;
}
__device__ __forceinline__ void mma16(float* c, const uint32_t* a, const uint32_t* b) {
    asm volatile(
        "mma.sync.aligned.m16n8k16.row.col.f32.bf16.bf16.f32 "
        "{%0,%1,%2,%3}, {%4,%5,%6,%7}, {%8,%9}, {%0,%1,%2,%3};"
        : "+f"(c[0]), "+f"(c[1]), "+f"(c[2]), "+f"(c[3])
        : "r"(a[0]), "r"(a[1]), "r"(a[2]), "r"(a[3]), "r"(b[0]), "r"(b[1]));
}
__device__ __forceinline__ void mma8(float* c, const uint32_t* a, const uint32_t* b) {
    asm volatile(
        "mma.sync.aligned.m16n8k8.row.col.f32.tf32.tf32.f32 "
        "{%0,%1,%2,%3}, {%4,%5,%6,%7}, {%8,%9}, {%0,%1,%2,%3};"
        : "+f"(c[0]), "+f"(c[1]), "+f"(c[2]), "+f"(c[3])
        : "r"(a[0]), "r"(a[1]), "r"(a[2]), "r"(a[3]), "r"(b[0]), "r"(b[1]));
}
__device__ __forceinline__ float4 bf4tof4(uint2 u) {
    __nv_bfloat162 a = *(__nv_bfloat162*)&u.x;
    __nv_bfloat162 b = *(__nv_bfloat162*)&u.y;
    return make_float4(__bfloat162float(a.x), __bfloat162float(a.y),
                       __bfloat162float(b.x), __bfloat162float(b.y));
}

// ---------------- small utility kernels ----------------
__global__ void zerof_k(float* p, int n) {
    int i = blockIdx.x * blockDim.x + threadIdx.x;
    if (i < n) p[i] = 0.0f;
}
__global__ void cnt_zero_k() {
    int i = blockIdx.x * blockDim.x + threadIdx.x;
    if (i < Nn) g_cnt[i] = 0;
}
__global__ void cnt_count_k(const int* __restrict__ dst) {
    int e = blockIdx.x * blockDim.x + threadIdx.x;
    if (e < Ee) atomicAdd(&g_cnt[dst[e]], 1);
}
__global__ void dinv_k() {
    int i = blockIdx.x * blockDim.x + threadIdx.x;
    if (i < Nn) g_dinv[i] = rsqrtf((float)g_cnt[i] + 1.0f);
}
__global__ void wpack_k(const float* __restrict__ W, int slot) {
    int i = blockIdx.x * blockDim.x + threadIdx.x;
    if (i >= WSLOT) return;
    int kk = i >> 8, n = i & 255;
    __nv_bfloat162 p = __floats2bfloat162_rn(W[(2 * kk) * 256 + n], W[(2 * kk + 1) * 256 + n]);
    g_wpack[slot][i] = *(uint32_t*)&p;
}
__global__ void embpack_k(const float* __restrict__ W) {
    int i = blockIdx.x * blockDim.x + threadIdx.x;
    if (i >= INf * Hh) return;
    float w = W[i];
    float h = __uint_as_float(f2tf(w));
    g_ewh[i] = h;
    g_ewl[i] = __uint_as_float(f2tf(w - h));
}

// ---------------- CSR build ----------------
__global__ void scan1_k() {
    __shared__ int sh[256];
    int i = blockIdx.x * 256 + threadIdx.x;
    int v = (i < Nn) ? g_cnt[i] : 0;
    sh[threadIdx.x] = v;
    __syncthreads();
    for (int off = 1; off < 256; off <<= 1) {
        int t = (threadIdx.x >= off) ? sh[threadIdx.x - off] : 0;
        __syncthreads();
        sh[threadIdx.x] += t;
        __syncthreads();
    }
    if (i < Nn) g_scan[i] = sh[threadIdx.x];
    if (threadIdx.x == 255) g_bsum[blockIdx.x] = sh[255];
}
__global__ void scan2_k(int nblk) {
    __shared__ int sh[256];
    int b = threadIdx.x;
    int v = (b < nblk) ? g_bsum[b] : 0;
    sh[b] = v;
    __syncthreads();
    for (int off = 1; off < 256; off <<= 1) {
        int t = (b >= off) ? sh[b - off] : 0;
        __syncthreads();
        sh[b] += t;
        __syncthreads();
    }
    if (b < nblk) g_bbase[b] = sh[b] - v;
}
__global__ void scan3_k() {
    int i = blockIdx.x * blockDim.x + threadIdx.x;
    if (i < Nn) {
        int off = g_scan[i] - g_cnt[i] + g_bbase[i >> 8];
        g_off[i] = off;
        g_fill[i] = off;
    }
}
__global__ void fill_k(const int* __restrict__ src, const int* __restrict__ dst) {
    int e = blockIdx.x * blockDim.x + threadIdx.x;
    if (e >= Ee) return;
    int s = src[e], d = dst[e];
    int p = atomicAdd(&g_fill[d], 1);
    g_esrc[p] = s;
    g_ecoef[p] = g_dinv[s] * g_dinv[d];
}

// ---------------- emb GEMM: tf32x3 tensor cores, h = x @ emb_W + b ----------------
__global__ __launch_bounds__(256) void emb_mma_k(
    const float* __restrict__ A, const float* __restrict__ bias, float* __restrict__ out)
{
    __shared__ uint32_t AsH[128][20], AsL[128][20];
    __shared__ uint32_t BsH[16][136], BsL[16][136];

    int tid = threadIdx.x;
    int wid = tid >> 5, lane = tid & 31;
    int m0 = blockIdx.y * 128, n0 = blockIdx.x * 128;
    int wm = (wid & 3) * 32, wn = (wid >> 2) * 64;
    int group = lane >> 2, tig = lane & 3;

    float acc[2][8][4];
#pragma unroll
    for (int mt = 0; mt < 2; mt++)
#pragma unroll
        for (int nt = 0; nt < 8; nt++)
#pragma unroll
            for (int q = 0; q < 4; q++) acc[mt][nt][q] = 0.0f;

    int arow = tid >> 1, acK = (tid & 1) * 8;
    int bkr = tid >> 4, bn8 = (tid & 15) * 8;
    bool vA = (m0 + arow) < Nn;
    float4 z4 = make_float4(0.f, 0.f, 0.f, 0.f);

    for (int kt = 0; kt < 8; kt++) {
        int k0 = kt * 16;
        float4 a0 = vA ? *(const float4*)(A + (size_t)(m0 + arow) * INf + k0 + acK) : z4;
        float4 a1 = vA ? *(const float4*)(A + (size_t)(m0 + arow) * INf + k0 + acK + 4) : z4;
        float av[8] = {a0.x, a0.y, a0.z, a0.w, a1.x, a1.y, a1.z, a1.w};
#pragma unroll
        for (int j = 0; j < 8; j++) {
            uint32_t hb = f2tf(av[j]);
            AsH[arow][acK + j] = hb;
            AsL[arow][acK + j] = f2tf(av[j] - __uint_as_float(hb));
        }
        const float* bh = g_ewh + (size_t)(k0 + bkr) * 256 + n0 + bn8;
        const float* bl = g_ewl + (size_t)(k0 + bkr) * 256 + n0 + bn8;
        *(float4*)&BsH[bkr][bn8]     = *(const float4*)(bh);
        *(float4*)&BsH[bkr][bn8 + 4] = *(const float4*)(bh + 4);
        *(float4*)&BsL[bkr][bn8]     = *(const float4*)(bl);
        *(float4*)&BsL[bkr][bn8 + 4] = *(const float4*)(bl + 4);
        __syncthreads();

#pragma unroll
        for (int ks = 0; ks < 2; ks++) {
            int kb = ks * 8;
            uint32_t ah[2][4], al[2][4];
#pragma unroll
            for (int mt = 0; mt < 2; mt++) {
                int r = wm + mt * 16 + group;
                ah[mt][0] = AsH[r][kb + tig];     ah[mt][1] = AsH[r + 8][kb + tig];
                ah[mt][2] = AsH[r][kb + tig + 4]; ah[mt][3] = AsH[r + 8][kb + tig + 4];
                al[mt][0] = AsL[r][kb + tig];     al[mt][1] = AsL[r + 8][kb + tig];
                al[mt][2] = AsL[r][kb + tig + 4]; al[mt][3] = AsL[r + 8][kb + tig + 4];
            }
            uint32_t bh2[8][2], bl2[8][2];
#pragma unroll
            for (int nt = 0; nt < 8; nt++) {
                int cc = wn + nt * 8 + group;
                bh2[nt][0] = BsH[kb + tig][cc]; bh2[nt][1] = BsH[kb + tig + 4][cc];
                bl2[nt][0] = BsL[kb + tig][cc]; bl2[nt][1] = BsL[kb + tig + 4][cc];
            }
#pragma unroll
            for (int mt = 0; mt < 2; mt++)
#pragma unroll
                for (int nt = 0; nt < 8; nt++) {
                    mma8(acc[mt][nt], ah[mt], bh2[nt]);
                    mma8(acc[mt][nt], ah[mt], bl2[nt]);
                    mma8(acc[mt][nt], al[mt], bh2[nt]);
                }
        }
        __syncthreads();
    }

#pragma unroll
    for (int mt = 0; mt < 2; mt++)
#pragma unroll
        for (int half = 0; half < 2; half++) {
            int row = m0 + wm + mt * 16 + group + half * 8;
            if (row >= Nn) continue;
#pragma unroll
            for (int nt = 0; nt < 8; nt++) {
                int col = n0 + wn + nt * 8 + 2 * tig;
                size_t base = (size_t)row * 256 + col;
                out[base]     = acc[mt][nt][half * 2 + 0] + bias[col];
                out[base + 1] = acc[mt][nt][half * 2 + 1] + bias[col + 1];
            }
        }
}

// ---------------- bf16 mma GEMM -> mb (bf16). NORMA: fused graphnorm+leaky on A ----------------
template <int NORMA, int ABF>
__global__ __launch_bounds__(256) void mmabf16_k(
    const void* __restrict__ Araw, const uint32_t* __restrict__ Bp,
    __nv_bfloat16* __restrict__ bout,
    const float* __restrict__ nAa, const float* __restrict__ nAb)
{
    __shared__ uint32_t As[128][20];
    __shared__ uint32_t Bs[16][136];

    int tid = threadIdx.x;
    int wid = tid >> 5, lane = tid & 31;
    int m0 = blockIdx.y * 128, n0 = blockIdx.x * 128;
    int wm = (wid & 3) * 32, wn = (wid >> 2) * 64;
    int group = lane >> 2, tig = lane & 3;

    float acc[2][8][4];
#pragma unroll
    for (int mt = 0; mt < 2; mt++)
#pragma unroll
        for (int nt = 0; nt < 8; nt++)
#pragma unroll
            for (int q = 0; q < 4; q++) acc[mt][nt][q] = 0.0f;

    int arow = tid >> 3, acK = (tid & 7) * 4;
    int bkr = tid >> 4, bn8 = (tid & 15) * 8;

    bool vAi[4];
    int ggA[4];
#pragma unroll
    for (int i = 0; i < 4; i++) {
        int r = m0 + arow + 32 * i;
        vAi[i] = r < Nn;
        ggA[i] = vAi[i] ? (r / NPGc) : 0;
    }

    const float* Af = (const float*)Araw;
    const __nv_bfloat16* Ab = (const __nv_bfloat16*)Araw;
    float4 paf[4];
    uint2 pab[4];
    uint4 pb[2];
    float4 z4 = make_float4(0.f, 0.f, 0.f, 0.f);
    uint2 z2 = make_uint2(0, 0);

#pragma unroll
    for (int i = 0; i < 4; i++) {
        int r = m0 + arow + 32 * i;
        if (ABF) pab[i] = vAi[i] ? *(const uint2*)(Ab + (size_t)r * 256 + acK) : z2;
        else     paf[i] = vAi[i] ? *(const float4*)(Af + (size_t)r * 256 + acK) : z4;
    }
#pragma unroll
    for (int j = 0; j < 2; j++)
        pb[j] = *(const uint4*)(Bp + (size_t)bkr * 256 + n0 + bn8 + 4 * j);

    for (int kt = 0; kt < 8; kt++) {
#pragma unroll
        for (int i = 0; i < 4; i++) {
            float4 w = ABF ? bf4tof4(pab[i]) : paf[i];
            if (NORMA) {
                if (vAi[i]) {
                    float4 a4 = *(const float4*)(nAa + ggA[i] * 256 + kt * 32 + acK);
                    float4 b4 = *(const float4*)(nAb + ggA[i] * 256 + kt * 32 + acK);
                    w.x = fmaf(w.x, a4.x, b4.x); w.x = w.x > 0.f ? w.x : 0.01f * w.x;
                    w.y = fmaf(w.y, a4.y, b4.y); w.y = w.y > 0.f ? w.y : 0.01f * w.y;
                    w.z = fmaf(w.z, a4.z, b4.z); w.z = w.z > 0.f ? w.z : 0.01f * w.z;
                    w.w = fmaf(w.w, a4.w, b4.w); w.w = w.w > 0.f ? w.w : 0.01f * w.w;
                }
            }
            As[arow + 32 * i][(acK >> 1) + 0] = packbf2(w.x, w.y);
            As[arow + 32 * i][(acK >> 1) + 1] = packbf2(w.z, w.w);
        }
#pragma unroll
        for (int j = 0; j < 2; j++)
            *(uint4*)&Bs[bkr][bn8 + 4 * j] = pb[j];
        __syncthreads();

        if (kt < 7) {
            int k0 = (kt + 1) * 32;
#pragma unroll
            for (int i = 0; i < 4; i++) {
                int r = m0 + arow + 32 * i;
                if (ABF) pab[i] = vAi[i] ? *(const uint2*)(Ab + (size_t)r * 256 + k0 + acK) : z2;
                else     paf[i] = vAi[i] ? *(const float4*)(Af + (size_t)r * 256 + k0 + acK) : z4;
            }
#pragma unroll
            for (int j = 0; j < 2; j++)
                pb[j] = *(const uint4*)(Bp + (size_t)((k0 >> 1) + bkr) * 256 + n0 + bn8 + 4 * j);
        }

#pragma unroll
        for (int s = 0; s < 2; s++) {
            uint32_t afr[2][4];
#pragma unroll
            for (int mt = 0; mt < 2; mt++) {
                int r = wm + mt * 16 + group;
                afr[mt][0] = As[r][s * 8 + tig];
                afr[mt][1] = As[r + 8][s * 8 + tig];
                afr[mt][2] = As[r][s * 8 + tig + 4];
                afr[mt][3] = As[r + 8][s * 8 + tig + 4];
            }
            uint32_t bfr[8][2];
#pragma unroll
            for (int nt = 0; nt < 8; nt++) {
                int cc = wn + nt * 8 + group;
                bfr[nt][0] = Bs[s * 8 + tig][cc];
                bfr[nt][1] = Bs[s * 8 + tig + 4][cc];
            }
#pragma unroll
            for (int mt = 0; mt < 2; mt++)
#pragma unroll
                for (int nt = 0; nt < 8; nt++) mma16(acc[mt][nt], afr[mt], bfr[nt]);
        }
        __syncthreads();
    }

#pragma unroll
    for (int mt = 0; mt < 2; mt++)
#pragma unroll
        for (int half = 0; half < 2; half++) {
            int row = m0 + wm + mt * 16 + group + half * 8;
            if (row >= Nn) continue;
#pragma unroll
            for (int nt = 0; nt < 8; nt++) {
                int col = n0 + wn + nt * 8 + 2 * tig;
                size_t base = (size_t)row * 256 + col;
                __nv_bfloat162 p = __floats2bfloat162_rn(acc[mt][nt][half * 2 + 0],
                                                         acc[mt][nt][half * 2 + 1]);
                *(__nv_bfloat162*)(bout + base) = p;
            }
        }
}

// ---------------- merged gate GEMM: K=512 + blend + residual ----------------
__global__ __launch_bounds__(256) void gate_k(
    const uint32_t* __restrict__ Bp, const float* __restrict__ gate_b,
    float* __restrict__ h)
{
    __shared__ uint32_t As[128][20];
    __shared__ uint32_t Bs[16][136];

    int tid = threadIdx.x;
    int wid = tid >> 5, lane = tid & 31;
    int m0 = blockIdx.y * 128, n0 = blockIdx.x * 128;
    int wm = (wid & 3) * 32, wn = (wid >> 2) * 64;
    int group = lane >> 2, tig = lane & 3;

    float acc[2][8][4];
#pragma unroll
    for (int mt = 0; mt < 2; mt++)
#pragma unroll
        for (int nt = 0; nt < 8; nt++)
#pragma unroll
            for (int q = 0; q < 4; q++) acc[mt][nt][q] = 0.0f;

    int arow = tid >> 3, acK = (tid & 7) * 4;
    int bkr = tid >> 4, bn8 = (tid & 15) * 8;

    bool vAi[4];
    int ggA[4];
#pragma unroll
    for (int i = 0; i < 4; i++) {
        int r = m0 + arow + 32 * i;
        vAi[i] = r < Nn;
        ggA[i] = vAi[i] ? (r / NPGc) : 0;
    }

    uint2 pab[4];
    uint4 pb[2];
    uint2 z2 = make_uint2(0, 0);

#pragma unroll
    for (int i = 0; i < 4; i++) {
        int r = m0 + arow + 32 * i;
        pab[i] = vAi[i] ? *(const uint2*)(g_cb + (size_t)r * 256 + acK) : z2;
    }
#pragma unroll
    for (int j = 0; j < 2; j++)
        pb[j] = *(const uint4*)(Bp + (size_t)bkr * 256 + n0 + bn8 + 4 * j);

    for (int kt = 0; kt < 16; kt++) {
        int khalf = kt >> 3;                 // 0: c-branch, 1: f-branch
        int koff = (kt & 7) * 32;
        const float* na = khalf ? g_af : g_ac;
        const float* nb = khalf ? g_bf : g_bc;
#pragma unroll
        for (int i = 0; i < 4; i++) {
            float4 w = bf4tof4(pab[i]);
            if (vAi[i]) {
                float4 a4 = *(const float4*)(na + ggA[i] * 256 + koff + acK);
                float4 b4 = *(const float4*)(nb + ggA[i] * 256 + koff + acK);
                w.x = fmaf(w.x, a4.x, b4.x); w.x = w.x > 0.f ? w.x : 0.01f * w.x;
                w.y = fmaf(w.y, a4.y, b4.y); w.y = w.y > 0.f ? w.y : 0.01f * w.y;
                w.z = fmaf(w.z, a4.z, b4.z); w.z = w.z > 0.f ? w.z : 0.01f * w.z;
                w.w = fmaf(w.w, a4.w, b4.w); w.w = w.w > 0.f ? w.w : 0.01f * w.w;
            }
            As[arow + 32 * i][(acK >> 1) + 0] = packbf2(w.x, w.y);
            As[arow + 32 * i][(acK >> 1) + 1] = packbf2(w.z, w.w);
        }
#pragma unroll
        for (int j = 0; j < 2; j++)
            *(uint4*)&Bs[bkr][bn8 + 4 * j] = pb[j];
        __syncthreads();

        if (kt < 15) {
            int nk = kt + 1;
            const __nv_bfloat16* Asrc = (nk < 8) ? g_cb : g_fbuf;
            int nkoff = (nk & 7) * 32;
#pragma unroll
            for (int i = 0; i < 4; i++) {
                int r = m0 + arow + 32 * i;
                pab[i] = vAi[i] ? *(const uint2*)(Asrc + (size_t)r * 256 + nkoff + acK) : z2;
            }
#pragma unroll
            for (int j = 0; j < 2; j++)
                pb[j] = *(const uint4*)(Bp + (size_t)((nk * 16) + bkr) * 256 + n0 + bn8 + 4 * j);
        }

#pragma unroll
        for (int s = 0; s < 2; s++) {
            uint32_t afr[2][4];
#pragma unroll
            for (int mt = 0; mt < 2; mt++) {
                int r = wm + mt * 16 + group;
                afr[mt][0] = As[r][s * 8 + tig];
                afr[mt][1] = As[r + 8][s * 8 + tig];
                afr[mt][2] = As[r][s * 8 + tig + 4];
                afr[mt][3] = As[r + 8][s * 8 + tig + 4];
            }
            uint32_t bfr[8][2];
#pragma unroll
            for (int nt = 0; nt < 8; nt++) {
                int cc = wn + nt * 8 + group;
                bfr[nt][0] = Bs[s * 8 + tig][cc];
                bfr[nt][1] = Bs[s * 8 + tig + 4][cc];
            }
#pragma unroll
            for (int mt = 0; mt < 2; mt++)
#pragma unroll
                for (int nt = 0; nt < 8; nt++) mma16(acc[mt][nt], afr[mt], bfr[nt]);
        }
        __syncthreads();
    }

    // epilogue: g = sigmoid(acc + gate_b); h = g*leaky(norm_c(c)) + (1-g)*leaky(norm_f(f)) + h
#pragma unroll
    for (int mt = 0; mt < 2; mt++)
#pragma unroll
        for (int half = 0; half < 2; half++) {
            int row = m0 + wm + mt * 16 + group + half * 8;
            if (row >= Nn) continue;
            int gg = row / NPGc;
#pragma unroll
            for (int nt = 0; nt < 8; nt++) {
                int col = n0 + wn + nt * 8 + 2 * tig;
                size_t base = (size_t)row * 256 + col;
                int cb2 = gg * 256 + col;
                float s0 = acc[mt][nt][half * 2 + 0] + gate_b[col];
                float s1 = acc[mt][nt][half * 2 + 1] + gate_b[col + 1];
                float gt0 = 1.0f / (1.0f + expf(-s0));
                float gt1 = 1.0f / (1.0f + expf(-s1));
                __nv_bfloat162 cv = *(const __nv_bfloat162*)(g_cb + base);
                __nv_bfloat162 fv = *(const __nv_bfloat162*)(g_fbuf + base);
                float c0 = fmaf(__bfloat162float(cv.x), g_ac[cb2],     g_bc[cb2]);
                float c1 = fmaf(__bfloat162float(cv.y), g_ac[cb2 + 1], g_bc[cb2 + 1]);
                c0 = c0 > 0.f ? c0 : 0.01f * c0;
                c1 = c1 > 0.f ? c1 : 0.01f * c1;
                float f0 = fmaf(__bfloat162float(fv.x), g_af[cb2],     g_bf[cb2]);
                float f1 = fmaf(__bfloat162float(fv.y), g_af[cb2 + 1], g_bf[cb2 + 1]);
                f0 = f0 > 0.f ? f0 : 0.01f * f0;
                f1 = f1 > 0.f ? f1 : 0.01f * f1;
                h[base]     = gt0 * c0 + (1.0f - gt0) * f0 + h[base];
                h[base + 1] = gt1 * c1 + (1.0f - gt1) * f1 + h[base + 1];
            }
        }
}

// ---------------- row normalize + tf32 hi/lo split ----------------
__global__ void rownorm_k() {
    int row = blockIdx.x;
    int t = threadIdx.x;
    float4 v = *(const float4*)(g_h + (size_t)row * Hh + t * 4);
    float s = v.x * v.x + v.y * v.y + v.z * v.z + v.w * v.w;
    __shared__ float sh[64];
    sh[t] = s;
    __syncthreads();
    for (int off = 32; off > 0; off >>= 1) {
        if (t < off) sh[t] += sh[t + off];
        __syncthreads();
    }
    float inv = 1.0f / (sqrtf(sh[0]) + 1e-12f);
    float n0 = v.x * inv, n1 = v.y * inv, n2 = v.z * inv, n3 = v.w * inv;
    float h0 = __uint_as_float(f2tf(n0));
    float h1 = __uint_as_float(f2tf(n1));
    float h2 = __uint_as_float(f2tf(n2));
    float h3 = __uint_as_float(f2tf(n3));
    *(float4*)(g_xh + (size_t)row * Hh + t * 4) = make_float4(h0, h1, h2, h3);
    *(float4*)(g_xl + (size_t)row * Hh + t * 4) =
        make_float4(__uint_as_float(f2tf(n0 - h0)), __uint_as_float(f2tf(n1 - h1)),
                    __uint_as_float(f2tf(n2 - h2)), __uint_as_float(f2tf(n3 - h3)));
}

// ---------------- top-3 insert ----------------
__device__ __forceinline__ void tk3(float v, int id, float* tv, int* ti) {
    if (v > tv[0] || (v == tv[0] && id < ti[0])) {
        tv[2] = tv[1]; ti[2] = ti[1];
        tv[1] = tv[0]; ti[1] = ti[0];
        tv[0] = v;     ti[0] = id;
    } else if (v > tv[1] || (v == tv[1] && id < ti[1])) {
        tv[2] = tv[1]; ti[2] = ti[1];
        tv[1] = v;     ti[1] = id;
    } else if (v > tv[2] || (v == tv[2] && id < ti[2])) {
        tv[2] = v;     ti[2] = id;
    }
}

// ---------------- fused 3xTF32 sim + top-3 ----------------
__global__ __launch_bounds__(256) void simtopk_mma_k() {
    int g = blockIdx.y;
    int i0 = blockIdx.x * 64;
    const float* XH = g_xh + (size_t)g * NPGc * Hh;
    const float* XL = g_xl + (size_t)g * NPGc * Hh;
    int goff = g * NPGc;

    __shared__ uint32_t Ah[64][20], Al[64][20], Bh[128][20], Bl[128][20];
    __shared__ float redv[4][64][3];
    __shared__ int   redi[4][64][3];

    int tid = threadIdx.x;
    int wid = tid >> 5, lane = tid & 31;
    int group = lane >> 2, tig = lane & 3;
    int wrow = (wid & 1) * 32, wcol = (wid >> 1) * 32;

    float tv[4][3];
    int ti[4][3];
#pragma unroll
    for (int r = 0; r < 4; r++)
#pragma unroll
        for (int c = 0; c < 3; c++) { tv[r][c] = -1e30f; ti[r][c] = 0x7fffffff; }

    int rA = tid >> 2, qA = (tid & 3) * 4;
    int rB = tid >> 1, qB = (tid & 1) * 8;
    bool vA = (i0 + rA) < NPGc;
    const float* ahp = XH + (size_t)(i0 + rA) * Hh + qA;
    const float* alp = XL + (size_t)(i0 + rA) * Hh + qA;
    float4 zh = make_float4(0.f, 0.f, 0.f, 0.f);

    for (int jt = 0; jt < 4; jt++) {
        int j0 = jt * 128;
        bool vB = (j0 + rB) < NPGc;
        const float* bhp = XH + (size_t)(j0 + rB) * Hh + qB;
        const float* blp = XL + (size_t)(j0 + rB) * Hh + qB;

        float acc[2][4][4];
#pragma unroll
        for (int mt = 0; mt < 2; mt++)
#pragma unroll
            for (int nt = 0; nt < 4; nt++)
#pragma unroll
                for (int q = 0; q < 4; q++) acc[mt][nt][q] = 0.0f;

        for (int kt = 0; kt < 16; kt++) {
            int k0 = kt * 16;
            float4 va_h = vA ? *(const float4*)(ahp + k0) : zh;
            float4 va_l = vA ? *(const float4*)(alp + k0) : zh;
            *(uint4*)&Ah[rA][qA] = *(uint4*)&va_h;
            *(uint4*)&Al[rA][qA] = *(uint4*)&va_l;
            float4 vb_h0 = vB ? *(const float4*)(bhp + k0) : zh;
            float4 vb_h1 = vB ? *(const float4*)(bhp + k0 + 4) : zh;
            float4 vb_l0 = vB ? *(const float4*)(blp + k0) : zh;
            float4 vb_l1 = vB ? *(const float4*)(blp + k0 + 4) : zh;
            *(uint4*)&Bh[rB][qB]     = *(uint4*)&vb_h0;
            *(uint4*)&Bh[rB][qB + 4] = *(uint4*)&vb_h1;
            *(uint4*)&Bl[rB][qB]     = *(uint4*)&vb_l0;
            *(uint4*)&Bl[rB][qB + 4] = *(uint4*)&vb_l1;
            __syncthreads();

#pragma unroll
            for (int ks = 0; ks < 2; ks++) {
                int kb = ks * 8;
                uint32_t ah[2][4], al[2][4];
#pragma unroll
                for (int mt = 0; mt < 2; mt++) {
                    int r = wrow + mt * 16 + group;
                    ah[mt][0] = Ah[r][kb + tig];     ah[mt][1] = Ah[r + 8][kb + tig];
                    ah[mt][2] = Ah[r][kb + tig + 4]; ah[mt][3] = Ah[r + 8][kb + tig + 4];
                    al[mt][0] = Al[r][kb + tig];     al[mt][1] = Al[r + 8][kb + tig];
                    al[mt][2] = Al[r][kb + tig + 4]; al[mt][3] = Al[r + 8][kb + tig + 4];
                }
                uint32_t bh[4][2], bl[4][2];
#pragma unroll
                for (int nt = 0; nt < 4; nt++) {
                    int cc = wcol + nt * 8 + group;
                    bh[nt][0] = Bh[cc][kb + tig]; bh[nt][1] = Bh[cc][kb + tig + 4];
                    bl[nt][0] = Bl[cc][kb + tig]; bl[nt][1] = Bl[cc][kb + tig + 4];
                }
#pragma unroll
                for (int mt = 0; mt < 2; mt++)
#pragma unroll
                    for (int nt = 0; nt < 4; nt++) {
                        mma8(acc[mt][nt], ah[mt], bh[nt]);
                        mma8(acc[mt][nt], ah[mt], bl[nt]);
                        mma8(acc[mt][nt], al[mt], bh[nt]);
                    }
            }
            __syncthreads();
        }

#pragma unroll
        for (int mt = 0; mt < 2; mt++)
#pragma unroll
            for (int nt = 0; nt < 4; nt++)
#pragma unroll
                for (int q = 0; q < 4; q++) {
                    int half = q >> 1, cbit = q & 1;
                    int col = j0 + wcol + nt * 8 + 2 * tig + cbit;
                    if (col < NPGc) {
                        int r = mt * 2 + half;
                        tk3(acc[mt][nt][q], goff + col, tv[r], ti[r]);
                    }
                }
    }

#pragma unroll
    for (int x = 1; x <= 2; x <<= 1) {
#pragma unroll
        for (int r = 0; r < 4; r++) {
            float ov[3]; int oi[3];
#pragma unroll
            for (int c = 0; c < 3; c++) {
                ov[c] = __shfl_xor_sync(0xffffffff, tv[r][c], x);
                oi[c] = __shfl_xor_sync(0xffffffff, ti[r][c], x);
            }
#pragma unroll
            for (int c = 0; c < 3; c++) tk3(ov[c], oi[c], tv[r], ti[r]);
        }
    }

    if (tig == 0) {
        int w4 = wid >> 1;
#pragma unroll
        for (int r = 0; r < 4; r++) {
            int mt = r >> 1, half = r & 1;
            int rowl = wrow + mt * 16 + half * 8 + group;
#pragma unroll
            for (int c = 0; c < 3; c++) {
                redv[w4][rowl][c] = tv[r][c];
                redi[w4][rowl][c] = ti[r][c];
            }
        }
    }
    __syncthreads();

    if (tid < 64) {
        int rowg = i0 + tid;
        if (rowg < NPGc) {
            float fv[3]; int fi[3];
#pragma unroll
            for (int c = 0; c < 3; c++) { fv[c] = redv[0][tid][c]; fi[c] = redi[0][tid][c]; }
#pragma unroll
            for (int w = 1; w < 4; w++)
#pragma unroll
                for (int c = 0; c < 3; c++) tk3(redv[w][tid][c], redi[w][tid][c], fv, fi);
            int* o = g_knn + (size_t)(goff + rowg) * 3;
            o[0] = fi[0]; o[1] = fi[1]; o[2] = fi[2];
        }
    }
}

// ---------------- gathers with fused stats + bf16 output ----------------
__device__ __forceinline__ void gather_epi(float4 acc, int tid, int blk,
                                           __nv_bfloat16* obuf, size_t obase) {
    __shared__ float sh1[1024], sh2[1024];
    uint2 p;
    p.x = packbf2(acc.x, acc.y);
    p.y = packbf2(acc.z, acc.w);
    *(uint2*)(obuf + obase) = p;
    *(float4*)&sh1[tid * 4] = acc;
    *(float4*)&sh2[tid * 4] = make_float4(acc.x * acc.x, acc.y * acc.y,
                                          acc.z * acc.z, acc.w * acc.w);
    __syncthreads();
    if (tid < 64) {
        float4 s1 = make_float4(0.f, 0.f, 0.f, 0.f);
        float4 s2 = make_float4(0.f, 0.f, 0.f, 0.f);
#pragma unroll
        for (int nd = 0; nd < 4; nd++) {
            float4 a = *(float4*)&sh1[(nd * 64 + tid) * 4];
            float4 b = *(float4*)&sh2[(nd * 64 + tid) * 4];
            s1.x += a.x; s1.y += a.y; s1.z += a.z; s1.w += a.w;
            s2.x += b.x; s2.y += b.y; s2.z += b.z; s2.w += b.w;
        }
        int g = (blk * 4) / NPGc;
        int base = g * 256 + tid * 4;
        atomicAdd(&g_s1[base + 0], s1.x); atomicAdd(&g_s1[base + 1], s1.y);
        atomicAdd(&g_s1[base + 2], s1.z); atomicAdd(&g_s1[base + 3], s1.w);
        atomicAdd(&g_s2[base + 0], s2.x); atomicAdd(&g_s2[base + 1], s2.y);
        atomicAdd(&g_s2[base + 2], s2.z); atomicAdd(&g_s2[base + 3], s2.w);
    }
}

__global__ __launch_bounds__(256) void conv_gather_k(const float* __restrict__ bias) {
    int tid = threadIdx.x;
    int t = blockIdx.x * 256 + tid;
    int n = t >> 6, q = t & 63;
    float d0 = g_dinv[n];
    float co = d0 * d0;
    float4 a = bf4tof4(*(const uint2*)(g_mb + (size_t)n * 256 + q * 4));
    float4 bv = ((const float4*)bias)[q];
    float4 acc = make_float4(a.x * co + bv.x, a.y * co + bv.y,
                             a.z * co + bv.z, a.w * co + bv.w);
    int off = g_off[n], cnt = g_cnt[n];
    for (int j = 0; j < cnt; j++) {
        int s = g_esrc[off + j];
        float cf = g_ecoef[off + j];
        float4 v = bf4tof4(*(const uint2*)(g_mb + (size_t)s * 256 + q * 4));
        acc.x += v.x * cf; acc.y += v.y * cf; acc.z += v.z * cf; acc.w += v.w * cf;
    }
    gather_epi(acc, tid, blockIdx.x, g_cb, (size_t)n * 256 + q * 4);
}

__global__ __launch_bounds__(256) void knn_agg_k(const float* __restrict__ bias) {
    int tid = threadIdx.x;
    int t = blockIdx.x * 256 + tid;
    int n = t >> 6, q = t & 63;
    int i0 = g_knn[n * 3 + 0], i1 = g_knn[n * 3 + 1], i2 = g_knn[n * 3 + 2];
    float4 a = bf4tof4(*(const uint2*)(g_mb + (size_t)n * 256 + q * 4));
    float4 b = bf4tof4(*(const uint2*)(g_mb + (size_t)i0 * 256 + q * 4));
    float4 c = bf4tof4(*(const uint2*)(g_mb + (size_t)i1 * 256 + q * 4));
    float4 d = bf4tof4(*(const uint2*)(g_mb + (size_t)i2 * 256 + q * 4));
    float4 bv = ((const float4*)bias)[q];
    float4 acc = make_float4(0.25f * (a.x + b.x + c.x + d.x) + bv.x,
                             0.25f * (a.y + b.y + c.y + d.y) + bv.y,
                             0.25f * (a.z + b.z + c.z + d.z) + bv.z,
                             0.25f * (a.w + b.w + c.w + d.w) + bv.w);
    gather_epi(acc, tid, blockIdx.x, g_fbuf, (size_t)n * 256 + q * 4);
}

// ---------------- finalize norm params (self-zeroing stats) ----------------
__global__ void finalize_k(const float* __restrict__ w, const float* __restrict__ b,
                           const float* __restrict__ ms,
                           float* __restrict__ alpha, float* __restrict__ beta) {
    int i = blockIdx.x * blockDim.x + threadIdx.x;
    if (i >= Gg * Hh) return;
    int cc = i & 255;
    float mean = g_s1[i] * (1.0f / NPGc);
    float ex2 = g_s2[i] * (1.0f / NPGc);
    float m = ms[cc];
    float var = ex2 - mean * mean * m * (2.0f - m);
    float a = w[cc] * rsqrtf(var + 1e-5f);
    alpha[i] = a;
    beta[i] = b[cc] - a * m * mean;
    g_s1[i] = 0.0f;
    g_s2[i] = 0.0f;
}

// ---------------- pooling ----------------
__global__ void pool_k(const float* __restrict__ buf, float* __restrict__ out, float wgt) {
    int b = blockIdx.x;
    int g = b / SPLIT, sp = b % SPLIT;
    int cc = threadIdx.x;
    int r0 = g * NPGc + sp * RPS;
    float s = 0.0f;
    for (int r = 0; r < RPS; r++) s += buf[(size_t)(r0 + r) * Hh + cc];
    atomicAdd(&out[g * Hh + cc], s * wgt * (1.0f / NPGc));
}

// ---------------- launch ----------------
extern "C" void kernel_launch(void* const* d_in, const int* in_sizes, int n_in,
                              void* d_out, int out_size) {
    const float* x       = (const float*)d_in[0];
    const int*   ei      = (const int*)d_in[1];
    const float* emb_W   = (const float*)d_in[3];
    const float* emb_b   = (const float*)d_in[4];
    const float* conv_W  = (const float*)d_in[5];
    const float* conv_b  = (const float*)d_in[6];
    const float* fconv_W = (const float*)d_in[7];
    const float* fconv_b = (const float*)d_in[8];
    const float* norm_w  = (const float*)d_in[9];
    const float* norm_b  = (const float*)d_in[10];
    const float* norm_ms = (const float*)d_in[11];
    const float* fnorm_w = (const float*)d_in[12];
    const float* fnorm_b = (const float*)d_in[13];
    const float* fnorm_ms= (const float*)d_in[14];
    const float* gate_W  = (const float*)d_in[15];
    const float* gate_b  = (const float*)d_in[16];
    float* out = (float*)d_out;

    const int* src = ei;
    const int* dst = ei + Ee;

    float *h, *ac, *bc, *af, *bf;
    __nv_bfloat16 *mb, *cb, *fb;
    uint32_t* wp;
    cudaGetSymbolAddress((void**)&h, g_h);
    cudaGetSymbolAddress((void**)&mb, g_mb);
    cudaGetSymbolAddress((void**)&cb, g_cb);
    cudaGetSymbolAddress((void**)&fb, g_fbuf);
    cudaGetSymbolAddress((void**)&wp, g_wpack);
    cudaGetSymbolAddress((void**)&ac, g_ac);
    cudaGetSymbolAddress((void**)&bc, g_bc);
    cudaGetSymbolAddress((void**)&af, g_af);
    cudaGetSymbolAddress((void**)&bf, g_bf);

    const int TPB = 256;
    const int MB = (Nn + 127) / 128;     // 391
    dim3 gemm_grid(2, MB);
    const int NBLK = (Nn + 255) / 256;   // 196
    const int WPB = (WSLOT + TPB - 1) / TPB;
    cudaStream_t ws = g_sx.ws;

    // ---- fork: worker stream handles weight packing + CSR build ----
    cudaEventRecord(g_sx.ev_fork, 0);
    cudaStreamWaitEvent(ws, g_sx.ev_fork, 0);

    // worker chain part 1 (independent of main chain buffers)
    wpack_k<<<WPB, TPB, 0, ws>>>(conv_W,              0);
    wpack_k<<<WPB, TPB, 0, ws>>>(conv_W + Hh * Hh,    1);
    wpack_k<<<WPB, TPB, 0, ws>>>(fconv_W,             2);
    wpack_k<<<WPB, TPB, 0, ws>>>(fconv_W + Hh * Hh,   3);
    wpack_k<<<WPB, TPB, 0, ws>>>(gate_W,              4);
    wpack_k<<<WPB, TPB, 0, ws>>>(gate_W + Hh * Hh,    5);
    cnt_zero_k<<<NBLK, TPB, 0, ws>>>();
    cnt_count_k<<<(Ee + TPB - 1) / TPB, TPB, 0, ws>>>(dst);
    dinv_k<<<NBLK, TPB, 0, ws>>>();
    scan1_k<<<NBLK, 256, 0, ws>>>();
    scan2_k<<<1, 256, 0, ws>>>(NBLK);
    scan3_k<<<NBLK, TPB, 0, ws>>>();
    fill_k<<<(Ee + TPB - 1) / TPB, TPB, 0, ws>>>(src, dst);

    // main chain: emb GEMM (produces h)
    zerof_k<<<(Gg * Hh + TPB - 1) / TPB, TPB>>>(out, Gg * Hh);
    embpack_k<<<(INf * Hh + TPB - 1) / TPB, TPB>>>(emb_W);
    emb_mma_k<<<gemm_grid, TPB>>>(x, emb_b, h);
    cudaEventRecord(g_sx.ev_h, 0);

    // worker chain part 2: layer-0 conv+fconv branch (needs h + CSR, NOT knn)
    cudaStreamWaitEvent(ws, g_sx.ev_h, 0);
    mmabf16_k<0, 0><<<gemm_grid, TPB, 0, ws>>>(h, wp + (size_t)0 * WSLOT, mb, nullptr, nullptr);
    conv_gather_k<<<(Nn * 64) / 256, TPB, 0, ws>>>(conv_b + 0 * Hh);
    finalize_k<<<(Gg * Hh + TPB - 1) / TPB, TPB, 0, ws>>>(norm_w + 0 * Hh, norm_b + 0 * Hh,
                                                          norm_ms + 0 * Hh, ac, bc);
    mmabf16_k<1, 1><<<gemm_grid, TPB, 0, ws>>>(cb, wp + (size_t)2 * WSLOT, mb, ac, bc);
    cudaEventRecord(g_sx.ev_join, ws);

    // main chain: cosine knn (concurrent with worker part 2)
    rownorm_k<<<Nn, 64>>>();
    simtopk_mma_k<<<dim3(8, Gg), TPB>>>();

    // ---- join: knn_agg needs g_knn (main) + g_mb (worker) ----
    cudaStreamWaitEvent(0, g_sx.ev_join, 0);

    // layer 0 remainder (main stream)
    knn_agg_k<<<(Nn * 64) / 256, TPB>>>(fconv_b + 0 * Hh);
    finalize_k<<<(Gg * Hh + TPB - 1) / TPB, TPB>>>(fnorm_w + 0 * Hh, fnorm_b + 0 * Hh,
                                                   fnorm_ms + 0 * Hh, af, bf);
    gate_k<<<gemm_grid, TPB>>>(wp + (size_t)4 * WSLOT, gate_b, h);
    pool_k<<<Gg * SPLIT, TPB>>>(h, out, 1.0f);

    // layer 1 (main stream)
    mmabf16_k<0, 0><<<gemm_grid, TPB>>>(h, wp + (size_t)1 * WSLOT, mb, nullptr, nullptr);
    conv_gather_k<<<(Nn * 64) / 256, TPB>>>(conv_b + 1 * Hh);
    finalize_k<<<(Gg * Hh + TPB - 1) / TPB, TPB>>>(norm_w + 1 * Hh, norm_b + 1 * Hh,
                                                   norm_ms + 1 * Hh, ac, bc);
    mmabf16_k<1, 1><<<gemm_grid, TPB>>>(cb, wp + (size_t)3 * WSLOT, mb, ac, bc);
    knn_agg_k<<<(Nn * 64) / 256, TPB>>>(fconv_b + 1 * Hh);
    finalize_k<<<(Gg * Hh + TPB - 1) / TPB, TPB>>>(fnorm_w + 1 * Hh, fnorm_b + 1 * Hh,
                                                   fnorm_ms + 1 * Hh, af, bf);
    gate_k<<<gemm_grid, TPB>>>(wp + (size_t)4 * WSLOT, gate_b, h);
    pool_k<<<Gg * SPLIT, TPB>>>(h, out, 2.0f);

    (void)in_sizes; (void)n_in; (void)out_size;
}